// round 1
// baseline (speedup 1.0000x reference)
#include <cuda_runtime.h>
#include <cuda_bf16.h>

// Problem constants
#define BATCH     4
#define SEQ       2048
#define DMODEL    1024
#define NHEAD     16
#define DEPTH     64
#define NTOK      (BATCH * SEQ)          // 8192
#define QK_SCALE  0.125f                 // 1/sqrt(64)

// ---------------------------------------------------------------------------
// Scratch buffers (allocations are forbidden; __device__ globals are allowed)
// ---------------------------------------------------------------------------
__device__ float g_qh [NTOK * DMODEL];   // [B,H,S,64] head-major, pre-scaled
__device__ float g_kh [NTOK * DMODEL];   // [B,H,S,64]
__device__ float g_vh [NTOK * DMODEL];   // [B,H,S,64]
__device__ float g_ctx[NTOK * DMODEL];   // [B,S,1024] token-major

// ---------------------------------------------------------------------------
// GEMM:  C = (A[M,K] @ W[N,K]^T + bias) * scale
// 128x128 tile, BK=16, 256 threads, 8x8 per-thread microtile.
// MODE 0: C[m*N + n]
// MODE 1: head-major: m=(b,s), n=(h,d) -> C[((b*NHEAD+h)*SEQ+s)*DEPTH+d]
// ---------------------------------------------------------------------------
template <int MODE>
__global__ void __launch_bounds__(256)
gemm_bias_kernel(const float* __restrict__ A,
                 const float* __restrict__ W,
                 const float* __restrict__ bias,
                 float* __restrict__ C,
                 int M, int N, int K, float scale)
{
    __shared__ float As[16][132];   // [k][m], padded
    __shared__ float Bs[16][132];   // [k][n], padded

    const int tid = threadIdx.x;
    const int tx  = tid & 15;       // n direction
    const int ty  = tid >> 4;       // m direction
    const int m0  = blockIdx.y * 128;
    const int n0  = blockIdx.x * 128;

    float acc[8][8];
    #pragma unroll
    for (int i = 0; i < 8; i++)
        #pragma unroll
        for (int j = 0; j < 8; j++) acc[i][j] = 0.0f;

    for (int k0 = 0; k0 < K; k0 += 16) {
        // Load 128x16 of A and 128x16 of W (as float4), store transposed.
        #pragma unroll
        for (int it = 0; it < 2; it++) {
            int f   = tid + it * 256;        // float4 index, 512 total
            int row = f >> 2;                // 0..127
            int kq  = f & 3;                 // which float4 in the 16-wide k
            float4 av = *(const float4*)(A + (size_t)(m0 + row) * K + k0 + kq * 4);
            As[kq * 4 + 0][row] = av.x;
            As[kq * 4 + 1][row] = av.y;
            As[kq * 4 + 2][row] = av.z;
            As[kq * 4 + 3][row] = av.w;
            float4 wv = *(const float4*)(W + (size_t)(n0 + row) * K + k0 + kq * 4);
            Bs[kq * 4 + 0][row] = wv.x;
            Bs[kq * 4 + 1][row] = wv.y;
            Bs[kq * 4 + 2][row] = wv.z;
            Bs[kq * 4 + 3][row] = wv.w;
        }
        __syncthreads();

        #pragma unroll
        for (int kk = 0; kk < 16; kk++) {
            float a[8], b[8];
            *(float4*)(a + 0) = *(const float4*)&As[kk][ty * 8 + 0];
            *(float4*)(a + 4) = *(const float4*)&As[kk][ty * 8 + 4];
            *(float4*)(b + 0) = *(const float4*)&Bs[kk][tx * 8 + 0];
            *(float4*)(b + 4) = *(const float4*)&Bs[kk][tx * 8 + 4];
            #pragma unroll
            for (int i = 0; i < 8; i++)
                #pragma unroll
                for (int j = 0; j < 8; j++)
                    acc[i][j] = fmaf(a[i], b[j], acc[i][j]);
        }
        __syncthreads();
    }

    // Epilogue
    #pragma unroll
    for (int i = 0; i < 8; i++) {
        int m = m0 + ty * 8 + i;
        #pragma unroll
        for (int j = 0; j < 8; j++) {
            int n = n0 + tx * 8 + j;
            float v = (acc[i][j] + bias[n]) * scale;
            if (MODE == 0) {
                C[(size_t)m * N + n] = v;
            } else {
                int b = m >> 11;          // / SEQ
                int s = m & (SEQ - 1);
                int h = n >> 6;           // / DEPTH
                int d = n & (DEPTH - 1);
                C[(((size_t)(b * NHEAD + h)) * SEQ + s) * DEPTH + d] = v;
            }
        }
    }
}

// ---------------------------------------------------------------------------
// Flash attention (fp32, causal).
// grid = (SEQ/64, BATCH*NHEAD), block = 256.
// Each CTA: 64-query tile. Thread (ty,tx): rows r0=ty*4..+3, keys/depth c0=tx*4..+3.
// Q already scaled by 1/sqrt(DEPTH) in projection.
// ---------------------------------------------------------------------------
#define ATT_PAD 68   // 64 + 4 (keeps float4 alignment, staggers banks)

__device__ __forceinline__ void load_tile64(const float* __restrict__ g,
                                            float* __restrict__ s, int tid)
{
    #pragma unroll
    for (int i = 0; i < 4; i++) {
        int f   = tid + i * 256;   // 1024 float4 total
        int row = f >> 4;          // 16 float4 per 64-float row
        int c4  = f & 15;
        *(float4*)(s + row * ATT_PAD + c4 * 4) =
            *(const float4*)(g + row * 64 + c4 * 4);
    }
}

extern __shared__ float att_smem[];

__global__ void __launch_bounds__(256)
attn_kernel(const float* __restrict__ Q,
            const float* __restrict__ K,
            const float* __restrict__ V,
            float* __restrict__ ctx)
{
    float* sq = att_smem;                      // 64 x ATT_PAD
    float* sk = sq + 64 * ATT_PAD;
    float* sv = sk + 64 * ATT_PAD;
    float* sp = sv + 64 * ATT_PAD;

    const int tid = threadIdx.x;
    const int tx  = tid & 15;
    const int ty  = tid >> 4;
    const int r0  = ty * 4;
    const int c0  = tx * 4;

    const int qt    = blockIdx.x;
    const int bh    = blockIdx.y;
    const int qbase = qt * 64;

    const float* Qb = Q + ((size_t)bh * SEQ + qbase) * DEPTH;
    const float* Kb = K + (size_t)bh * SEQ * DEPTH;
    const float* Vb = V + (size_t)bh * SEQ * DEPTH;

    load_tile64(Qb, sq, tid);

    float m_i[4], l_i[4], acc[4][4];
    #pragma unroll
    for (int i = 0; i < 4; i++) {
        m_i[i] = -1e30f;
        l_i[i] = 0.0f;
        #pragma unroll
        for (int j = 0; j < 4; j++) acc[i][j] = 0.0f;
    }

    for (int kt = 0; kt <= qt; kt++) {
        __syncthreads();   // protect sk/sv/sp from previous iteration
        load_tile64(Kb + (size_t)kt * 64 * DEPTH, sk, tid);
        load_tile64(Vb + (size_t)kt * 64 * DEPTH, sv, tid);
        __syncthreads();

        // ---- scores: s[i][j] = q_row(r0+i) . k_row(c0+j)
        float sc[4][4];
        #pragma unroll
        for (int i = 0; i < 4; i++)
            #pragma unroll
            for (int j = 0; j < 4; j++) sc[i][j] = 0.0f;

        #pragma unroll 4
        for (int d0 = 0; d0 < 64; d0 += 4) {
            float qv[4][4], kv[4][4];
            #pragma unroll
            for (int i = 0; i < 4; i++)
                *(float4*)qv[i] = *(const float4*)(sq + (r0 + i) * ATT_PAD + d0);
            #pragma unroll
            for (int j = 0; j < 4; j++)
                *(float4*)kv[j] = *(const float4*)(sk + (c0 + j) * ATT_PAD + d0);
            #pragma unroll
            for (int i = 0; i < 4; i++)
                #pragma unroll
                for (int j = 0; j < 4; j++)
                    #pragma unroll
                    for (int d = 0; d < 4; d++)
                        sc[i][j] = fmaf(qv[i][d], kv[j][d], sc[i][j]);
        }

        // ---- causal mask (diagonal tile only)
        if (kt == qt) {
            #pragma unroll
            for (int i = 0; i < 4; i++)
                #pragma unroll
                for (int j = 0; j < 4; j++)
                    if (c0 + j > r0 + i) sc[i][j] = -1e30f;
        }

        // ---- online softmax update
        #pragma unroll
        for (int i = 0; i < 4; i++) {
            float rmax = fmaxf(fmaxf(sc[i][0], sc[i][1]), fmaxf(sc[i][2], sc[i][3]));
            #pragma unroll
            for (int off = 8; off >= 1; off >>= 1)
                rmax = fmaxf(rmax, __shfl_xor_sync(0xffffffffu, rmax, off, 16));
            float mn    = fmaxf(m_i[i], rmax);
            float alpha = __expf(m_i[i] - mn);
            m_i[i] = mn;
            float ssum = 0.0f;
            #pragma unroll
            for (int j = 0; j < 4; j++) {
                float p = __expf(sc[i][j] - mn);
                sc[i][j] = p;
                ssum += p;
            }
            #pragma unroll
            for (int off = 8; off >= 1; off >>= 1)
                ssum += __shfl_xor_sync(0xffffffffu, ssum, off, 16);
            l_i[i] = l_i[i] * alpha + ssum;
            #pragma unroll
            for (int j = 0; j < 4; j++) acc[i][j] *= alpha;
            // stash P for the PV product
            *(float4*)(sp + (r0 + i) * ATT_PAD + c0) = *(float4*)sc[i];
        }
        __syncthreads();

        // ---- acc += P @ V  (thread: rows r0.., depth dims c0..)
        #pragma unroll 4
        for (int k0 = 0; k0 < 64; k0 += 4) {
            float pv[4][4], vv[4][4];
            #pragma unroll
            for (int i = 0; i < 4; i++)
                *(float4*)pv[i] = *(const float4*)(sp + (r0 + i) * ATT_PAD + k0);
            #pragma unroll
            for (int kk = 0; kk < 4; kk++)
                *(float4*)vv[kk] = *(const float4*)(sv + (k0 + kk) * ATT_PAD + c0);
            #pragma unroll
            for (int i = 0; i < 4; i++)
                #pragma unroll
                for (int j = 0; j < 4; j++)
                    #pragma unroll
                    for (int kk = 0; kk < 4; kk++)
                        acc[i][j] = fmaf(pv[i][kk], vv[kk][j], acc[i][j]);
        }
    }

    // ---- finalize, write ctx in token-major [B,S,1024]
    const int b = bh >> 4;
    const int h = bh & 15;
    #pragma unroll
    for (int i = 0; i < 4; i++) {
        int   qi  = qbase + r0 + i;
        float inv = 1.0f / l_i[i];
        float4 o;
        o.x = acc[i][0] * inv;
        o.y = acc[i][1] * inv;
        o.z = acc[i][2] * inv;
        o.w = acc[i][3] * inv;
        *(float4*)(ctx + (((size_t)b * SEQ + qi) * DMODEL) + h * DEPTH + c0) = o;
    }
}

// ---------------------------------------------------------------------------
// Launch
// ---------------------------------------------------------------------------
extern "C" void kernel_launch(void* const* d_in, const int* in_sizes, int n_in,
                              void* d_out, int out_size)
{
    const float* q       = (const float*)d_in[0];
    const float* k       = (const float*)d_in[1];
    const float* v       = (const float*)d_in[2];
    const float* wq_w    = (const float*)d_in[3];
    const float* wq_b    = (const float*)d_in[4];
    const float* wk_w    = (const float*)d_in[5];
    const float* wk_b    = (const float*)d_in[6];
    const float* wv_w    = (const float*)d_in[7];
    const float* wv_b    = (const float*)d_in[8];
    const float* dense_w = (const float*)d_in[9];
    const float* dense_b = (const float*)d_in[10];
    float* out           = (float*)d_out;

    float *qh, *kh, *vh, *ctx;
    cudaGetSymbolAddress((void**)&qh,  g_qh);
    cudaGetSymbolAddress((void**)&kh,  g_kh);
    cudaGetSymbolAddress((void**)&vh,  g_vh);
    cudaGetSymbolAddress((void**)&ctx, g_ctx);

    const dim3 ggrid(DMODEL / 128, NTOK / 128);   // (8, 64)
    const dim3 gblk(256);

    // Projections -> head-major; fold softmax scale into Q.
    gemm_bias_kernel<1><<<ggrid, gblk>>>(q, wq_w, wq_b, qh, NTOK, DMODEL, DMODEL, QK_SCALE);
    gemm_bias_kernel<1><<<ggrid, gblk>>>(k, wk_w, wk_b, kh, NTOK, DMODEL, DMODEL, 1.0f);
    gemm_bias_kernel<1><<<ggrid, gblk>>>(v, wv_w, wv_b, vh, NTOK, DMODEL, DMODEL, 1.0f);

    // Attention
    const int att_smem_bytes = 4 * 64 * ATT_PAD * (int)sizeof(float);  // 69632
    cudaFuncSetAttribute(attn_kernel, cudaFuncAttributeMaxDynamicSharedMemorySize,
                         att_smem_bytes);
    dim3 agrid(SEQ / 64, BATCH * NHEAD);          // (32, 64)
    attn_kernel<<<agrid, 256, att_smem_bytes>>>(qh, kh, vh, ctx);

    // Output dense
    gemm_bias_kernel<0><<<ggrid, gblk>>>(ctx, dense_w, dense_b, out, NTOK, DMODEL, DMODEL, 1.0f);
}

// round 4
// speedup vs baseline: 1.6546x; 1.6546x over previous
#include <cuda_runtime.h>
#include <cuda_bf16.h>
#include <cstdint>

// Problem constants
#define BATCH     4
#define SEQ       2048
#define DMODEL    1024
#define NHEAD     16
#define DEPTH     64
#define NTOK      (BATCH * SEQ)          // 8192
#define QK_SCALE  0.125f                 // 1/sqrt(64)

// ---------------------------------------------------------------------------
// Scratch buffers (allocations are forbidden; __device__ globals are allowed)
// ---------------------------------------------------------------------------
__device__ float g_qh [NTOK * DMODEL];   // [B,H,S,64] head-major, pre-scaled
__device__ float g_kh [NTOK * DMODEL];   // [B,H,S,64]
__device__ float g_vh [NTOK * DMODEL];   // [B,H,S,64]
__device__ float g_ctx[NTOK * DMODEL];   // [B,S,1024] token-major

// ---------------------------------------------------------------------------
// TF32 helpers
// ---------------------------------------------------------------------------
__device__ __forceinline__ uint32_t f2tf32(float x) {
    uint32_t r;
    asm("cvt.rna.tf32.f32 %0, %1;" : "=r"(r) : "f"(x));
    return r;
}

__device__ __forceinline__ void mma_tf32(float d[4],
                                         const uint32_t a[4],
                                         const uint32_t b[2]) {
    asm volatile(
        "mma.sync.aligned.m16n8k8.row.col.f32.tf32.tf32.f32 "
        "{%0,%1,%2,%3}, {%4,%5,%6,%7}, {%8,%9}, {%0,%1,%2,%3};\n"
        : "+f"(d[0]), "+f"(d[1]), "+f"(d[2]), "+f"(d[3])
        : "r"(a[0]), "r"(a[1]), "r"(a[2]), "r"(a[3]),
          "r"(b[0]), "r"(b[1]));
}

// ---------------------------------------------------------------------------
// TF32 GEMM: C = (A[M,K] @ W[N,K]^T + bias) * scale
// 128x128 tile, BK=32, 256 threads (8 warps as 2x4), warp tile 64x32.
// MODE 0: C[m*N + n]   MODE 1: head-major scatter (m=(b,s), n=(h,d)).
// ---------------------------------------------------------------------------
#define GPAD 36   // smem row pitch (floats); frag LDS + STS.128 conflict-free

template <int MODE>
__global__ void __launch_bounds__(256, 2)
gemm_tf32_kernel(const float* __restrict__ A,
                 const float* __restrict__ W,
                 const float* __restrict__ bias,
                 float* __restrict__ C,
                 int M, int N, int K, float scale)
{
    __shared__ float As[128][GPAD];
    __shared__ float Bs[128][GPAD];

    const int tid  = threadIdx.x;
    const int warp = tid >> 5;
    const int lane = tid & 31;
    const int wm   = (warp >> 2) * 64;    // warp m offset: 0 / 64
    const int wn   = (warp & 3) * 32;     // warp n offset: 0/32/64/96
    const int g    = lane >> 2;           // group id  0..7
    const int th   = lane & 3;            // thread in group 0..3
    const int m0   = blockIdx.y * 128;
    const int n0   = blockIdx.x * 128;

    float acc[4][4][4];
    #pragma unroll
    for (int mi = 0; mi < 4; mi++)
        #pragma unroll
        for (int ni = 0; ni < 4; ni++)
            #pragma unroll
            for (int r = 0; r < 4; r++) acc[mi][ni][r] = 0.0f;

    // Global load mapping: f = tid + i*256 -> row = f>>3 (0..127), q = f&7
    const int grow = tid >> 3;            // base row, +32 per i
    const int gq   = tid & 7;             // float4 index within 32-wide k
    const float* Abase = A + (size_t)(m0 + grow) * K + gq * 4;
    const float* Wbase = W + (size_t)(n0 + grow) * K + gq * 4;

    float4 ra[4], rb[4];
    #pragma unroll
    for (int i = 0; i < 4; i++) {
        ra[i] = *(const float4*)(Abase + (size_t)(i * 32) * K);
        rb[i] = *(const float4*)(Wbase + (size_t)(i * 32) * K);
    }

    for (int k0 = 0; k0 < K; k0 += 32) {
        // Store tiles to smem, rounding to tf32.
        #pragma unroll
        for (int i = 0; i < 4; i++) {
            uint4 ua = make_uint4(f2tf32(ra[i].x), f2tf32(ra[i].y),
                                  f2tf32(ra[i].z), f2tf32(ra[i].w));
            uint4 ub = make_uint4(f2tf32(rb[i].x), f2tf32(rb[i].y),
                                  f2tf32(rb[i].z), f2tf32(rb[i].w));
            *(uint4*)&As[grow + i * 32][gq * 4] = ua;
            *(uint4*)&Bs[grow + i * 32][gq * 4] = ub;
        }
        __syncthreads();

        // Prefetch next k-chunk while MMAs run.
        if (k0 + 32 < K) {
            #pragma unroll
            for (int i = 0; i < 4; i++) {
                ra[i] = *(const float4*)(Abase + (size_t)(i * 32) * K + k0 + 32);
                rb[i] = *(const float4*)(Wbase + (size_t)(i * 32) * K + k0 + 32);
            }
        }

        #pragma unroll
        for (int k8 = 0; k8 < 4; k8++) {
            uint32_t af[4][4], bf[4][2];
            #pragma unroll
            for (int mi = 0; mi < 4; mi++) {
                const float* p = &As[wm + mi * 16 + g][k8 * 8 + th];
                af[mi][0] = __float_as_uint(p[0]);
                af[mi][1] = __float_as_uint(p[8 * GPAD]);
                af[mi][2] = __float_as_uint(p[4]);
                af[mi][3] = __float_as_uint(p[8 * GPAD + 4]);
            }
            #pragma unroll
            for (int ni = 0; ni < 4; ni++) {
                const float* p = &Bs[wn + ni * 8 + g][k8 * 8 + th];
                bf[ni][0] = __float_as_uint(p[0]);
                bf[ni][1] = __float_as_uint(p[4]);
            }
            #pragma unroll
            for (int mi = 0; mi < 4; mi++)
                #pragma unroll
                for (int ni = 0; ni < 4; ni++)
                    mma_tf32(acc[mi][ni], af[mi], bf[ni]);
        }
        __syncthreads();
    }

    // Epilogue: d0=(g,2th) d1=(g,2th+1) d2=(g+8,2th) d3=(g+8,2th+1)
    #pragma unroll
    for (int mi = 0; mi < 4; mi++) {
        #pragma unroll
        for (int ni = 0; ni < 4; ni++) {
            const int n  = n0 + wn + ni * 8 + th * 2;
            const float2 bv = *(const float2*)(bias + n);
            const int mA = m0 + wm + mi * 16 + g;
            const int mB = mA + 8;
            float2 vA, vB;
            vA.x = (acc[mi][ni][0] + bv.x) * scale;
            vA.y = (acc[mi][ni][1] + bv.y) * scale;
            vB.x = (acc[mi][ni][2] + bv.x) * scale;
            vB.y = (acc[mi][ni][3] + bv.y) * scale;
            if (MODE == 0) {
                *(float2*)(C + (size_t)mA * N + n) = vA;
                *(float2*)(C + (size_t)mB * N + n) = vB;
            } else {
                const int h = n >> 6;
                const int d = n & (DEPTH - 1);
                {
                    const int b = mA >> 11, s = mA & (SEQ - 1);
                    *(float2*)(C + (((size_t)(b * NHEAD + h)) * SEQ + s) * DEPTH + d) = vA;
                }
                {
                    const int b = mB >> 11, s = mB & (SEQ - 1);
                    *(float2*)(C + (((size_t)(b * NHEAD + h)) * SEQ + s) * DEPTH + d) = vB;
                }
            }
        }
    }
}

// ---------------------------------------------------------------------------
// Flash attention (fp32, causal) — unchanged from round 1 baseline.
// grid = (SEQ/64, BATCH*NHEAD), block = 256.
// ---------------------------------------------------------------------------
#define ATT_PAD 68

__device__ __forceinline__ void load_tile64(const float* __restrict__ g,
                                            float* __restrict__ s, int tid)
{
    #pragma unroll
    for (int i = 0; i < 4; i++) {
        int f   = tid + i * 256;
        int row = f >> 4;
        int c4  = f & 15;
        *(float4*)(s + row * ATT_PAD + c4 * 4) =
            *(const float4*)(g + row * 64 + c4 * 4);
    }
}

extern __shared__ float att_smem[];

__global__ void __launch_bounds__(256)
attn_kernel(const float* __restrict__ Q,
            const float* __restrict__ K,
            const float* __restrict__ V,
            float* __restrict__ ctx)
{
    float* sq = att_smem;
    float* sk = sq + 64 * ATT_PAD;
    float* sv = sk + 64 * ATT_PAD;
    float* sp = sv + 64 * ATT_PAD;

    const int tid = threadIdx.x;
    const int tx  = tid & 15;
    const int ty  = tid >> 4;
    const int r0  = ty * 4;
    const int c0  = tx * 4;

    const int qt    = blockIdx.x;
    const int bh    = blockIdx.y;
    const int qbase = qt * 64;

    const float* Qb = Q + ((size_t)bh * SEQ + qbase) * DEPTH;
    const float* Kb = K + (size_t)bh * SEQ * DEPTH;
    const float* Vb = V + (size_t)bh * SEQ * DEPTH;

    load_tile64(Qb, sq, tid);

    float m_i[4], l_i[4], acc[4][4];
    #pragma unroll
    for (int i = 0; i < 4; i++) {
        m_i[i] = -1e30f;
        l_i[i] = 0.0f;
        #pragma unroll
        for (int j = 0; j < 4; j++) acc[i][j] = 0.0f;
    }

    for (int kt = 0; kt <= qt; kt++) {
        __syncthreads();
        load_tile64(Kb + (size_t)kt * 64 * DEPTH, sk, tid);
        load_tile64(Vb + (size_t)kt * 64 * DEPTH, sv, tid);
        __syncthreads();

        float sc[4][4];
        #pragma unroll
        for (int i = 0; i < 4; i++)
            #pragma unroll
            for (int j = 0; j < 4; j++) sc[i][j] = 0.0f;

        #pragma unroll 4
        for (int d0 = 0; d0 < 64; d0 += 4) {
            float qv[4][4], kv[4][4];
            #pragma unroll
            for (int i = 0; i < 4; i++)
                *(float4*)qv[i] = *(const float4*)(sq + (r0 + i) * ATT_PAD + d0);
            #pragma unroll
            for (int j = 0; j < 4; j++)
                *(float4*)kv[j] = *(const float4*)(sk + (c0 + j) * ATT_PAD + d0);
            #pragma unroll
            for (int i = 0; i < 4; i++)
                #pragma unroll
                for (int j = 0; j < 4; j++)
                    #pragma unroll
                    for (int d = 0; d < 4; d++)
                        sc[i][j] = fmaf(qv[i][d], kv[j][d], sc[i][j]);
        }

        if (kt == qt) {
            #pragma unroll
            for (int i = 0; i < 4; i++)
                #pragma unroll
                for (int j = 0; j < 4; j++)
                    if (c0 + j > r0 + i) sc[i][j] = -1e30f;
        }

        #pragma unroll
        for (int i = 0; i < 4; i++) {
            float rmax = fmaxf(fmaxf(sc[i][0], sc[i][1]), fmaxf(sc[i][2], sc[i][3]));
            #pragma unroll
            for (int off = 8; off >= 1; off >>= 1)
                rmax = fmaxf(rmax, __shfl_xor_sync(0xffffffffu, rmax, off, 16));
            float mn    = fmaxf(m_i[i], rmax);
            float alpha = __expf(m_i[i] - mn);
            m_i[i] = mn;
            float ssum = 0.0f;
            #pragma unroll
            for (int j = 0; j < 4; j++) {
                float p = __expf(sc[i][j] - mn);
                sc[i][j] = p;
                ssum += p;
            }
            #pragma unroll
            for (int off = 8; off >= 1; off >>= 1)
                ssum += __shfl_xor_sync(0xffffffffu, ssum, off, 16);
            l_i[i] = l_i[i] * alpha + ssum;
            #pragma unroll
            for (int j = 0; j < 4; j++) acc[i][j] *= alpha;
            *(float4*)(sp + (r0 + i) * ATT_PAD + c0) = *(float4*)sc[i];
        }
        __syncthreads();

        #pragma unroll 4
        for (int k0 = 0; k0 < 64; k0 += 4) {
            float pv[4][4], vv[4][4];
            #pragma unroll
            for (int i = 0; i < 4; i++)
                *(float4*)pv[i] = *(const float4*)(sp + (r0 + i) * ATT_PAD + k0);
            #pragma unroll
            for (int kk = 0; kk < 4; kk++)
                *(float4*)vv[kk] = *(const float4*)(sv + (k0 + kk) * ATT_PAD + c0);
            #pragma unroll
            for (int i = 0; i < 4; i++)
                #pragma unroll
                for (int j = 0; j < 4; j++)
                    #pragma unroll
                    for (int kk = 0; kk < 4; kk++)
                        acc[i][j] = fmaf(pv[i][kk], vv[kk][j], acc[i][j]);
        }
    }

    const int b = bh >> 4;
    const int h = bh & 15;
    #pragma unroll
    for (int i = 0; i < 4; i++) {
        int   qi  = qbase + r0 + i;
        float inv = 1.0f / l_i[i];
        float4 o;
        o.x = acc[i][0] * inv;
        o.y = acc[i][1] * inv;
        o.z = acc[i][2] * inv;
        o.w = acc[i][3] * inv;
        *(float4*)(ctx + (((size_t)b * SEQ + qi) * DMODEL) + h * DEPTH + c0) = o;
    }
}

// ---------------------------------------------------------------------------
// Launch
// ---------------------------------------------------------------------------
extern "C" void kernel_launch(void* const* d_in, const int* in_sizes, int n_in,
                              void* d_out, int out_size)
{
    const float* q       = (const float*)d_in[0];
    const float* k       = (const float*)d_in[1];
    const float* v       = (const float*)d_in[2];
    const float* wq_w    = (const float*)d_in[3];
    const float* wq_b    = (const float*)d_in[4];
    const float* wk_w    = (const float*)d_in[5];
    const float* wk_b    = (const float*)d_in[6];
    const float* wv_w    = (const float*)d_in[7];
    const float* wv_b    = (const float*)d_in[8];
    const float* dense_w = (const float*)d_in[9];
    const float* dense_b = (const float*)d_in[10];
    float* out           = (float*)d_out;

    float *qh, *kh, *vh, *ctx;
    cudaGetSymbolAddress((void**)&qh,  g_qh);
    cudaGetSymbolAddress((void**)&kh,  g_kh);
    cudaGetSymbolAddress((void**)&vh,  g_vh);
    cudaGetSymbolAddress((void**)&ctx, g_ctx);

    const dim3 ggrid(DMODEL / 128, NTOK / 128);   // (8, 64)
    const dim3 gblk(256);

    // Projections -> head-major; fold softmax scale into Q.
    gemm_tf32_kernel<1><<<ggrid, gblk>>>(q, wq_w, wq_b, qh, NTOK, DMODEL, DMODEL, QK_SCALE);
    gemm_tf32_kernel<1><<<ggrid, gblk>>>(k, wk_w, wk_b, kh, NTOK, DMODEL, DMODEL, 1.0f);
    gemm_tf32_kernel<1><<<ggrid, gblk>>>(v, wv_w, wv_b, vh, NTOK, DMODEL, DMODEL, 1.0f);

    // Attention
    const int att_smem_bytes = 4 * 64 * ATT_PAD * (int)sizeof(float);  // 69632
    cudaFuncSetAttribute(attn_kernel, cudaFuncAttributeMaxDynamicSharedMemorySize,
                         att_smem_bytes);
    dim3 agrid(SEQ / 64, BATCH * NHEAD);          // (32, 64)
    attn_kernel<<<agrid, 256, att_smem_bytes>>>(qh, kh, vh, ctx);

    // Output dense
    gemm_tf32_kernel<0><<<ggrid, gblk>>>(ctx, dense_w, dense_b, out, NTOK, DMODEL, DMODEL, 1.0f);
}

// round 7
// speedup vs baseline: 3.5285x; 2.1326x over previous
#include <cuda_runtime.h>
#include <cuda_bf16.h>
#include <cstdint>

// Problem constants
#define BATCH     4
#define SEQ       2048
#define DMODEL    1024
#define NHEAD     16
#define DEPTH     64
#define NTOK      (BATCH * SEQ)          // 8192
#define QK_SCALE  0.125f                 // 1/sqrt(64)

// ---------------------------------------------------------------------------
// Scratch buffers (allocations are forbidden; __device__ globals are allowed)
// ---------------------------------------------------------------------------
__device__ float g_qh [NTOK * DMODEL];   // [B,H,S,64] head-major, pre-scaled
__device__ float g_kh [NTOK * DMODEL];   // [B,H,S,64]
__device__ float g_vh [NTOK * DMODEL];   // [B,H,S,64]
__device__ float g_ctx[NTOK * DMODEL];   // [B,S,1024] token-major

// ---------------------------------------------------------------------------
// TF32 helpers
// ---------------------------------------------------------------------------
__device__ __forceinline__ uint32_t f2tf32(float x) {
    uint32_t r;
    asm("cvt.rna.tf32.f32 %0, %1;" : "=r"(r) : "f"(x));
    return r;
}

__device__ __forceinline__ void mma_tf32(float d[4],
                                         const uint32_t a[4],
                                         const uint32_t b[2]) {
    asm volatile(
        "mma.sync.aligned.m16n8k8.row.col.f32.tf32.tf32.f32 "
        "{%0,%1,%2,%3}, {%4,%5,%6,%7}, {%8,%9}, {%0,%1,%2,%3};\n"
        : "+f"(d[0]), "+f"(d[1]), "+f"(d[2]), "+f"(d[3])
        : "r"(a[0]), "r"(a[1]), "r"(a[2]), "r"(a[3]),
          "r"(b[0]), "r"(b[1]));
}

// ---------------------------------------------------------------------------
// TF32 GEMM: C = (A[M,K] @ W[N,K]^T + bias) * scale   (proven, unchanged)
// ---------------------------------------------------------------------------
#define GPAD 36

template <int MODE>
__global__ void __launch_bounds__(256, 2)
gemm_tf32_kernel(const float* __restrict__ A,
                 const float* __restrict__ W,
                 const float* __restrict__ bias,
                 float* __restrict__ C,
                 int M, int N, int K, float scale)
{
    __shared__ float As[128][GPAD];
    __shared__ float Bs[128][GPAD];

    const int tid  = threadIdx.x;
    const int warp = tid >> 5;
    const int lane = tid & 31;
    const int wm   = (warp >> 2) * 64;
    const int wn   = (warp & 3) * 32;
    const int g    = lane >> 2;
    const int th   = lane & 3;
    const int m0   = blockIdx.y * 128;
    const int n0   = blockIdx.x * 128;

    float acc[4][4][4];
    #pragma unroll
    for (int mi = 0; mi < 4; mi++)
        #pragma unroll
        for (int ni = 0; ni < 4; ni++)
            #pragma unroll
            for (int r = 0; r < 4; r++) acc[mi][ni][r] = 0.0f;

    const int grow = tid >> 3;
    const int gq   = tid & 7;
    const float* Abase = A + (size_t)(m0 + grow) * K + gq * 4;
    const float* Wbase = W + (size_t)(n0 + grow) * K + gq * 4;

    float4 ra[4], rb[4];
    #pragma unroll
    for (int i = 0; i < 4; i++) {
        ra[i] = *(const float4*)(Abase + (size_t)(i * 32) * K);
        rb[i] = *(const float4*)(Wbase + (size_t)(i * 32) * K);
    }

    for (int k0 = 0; k0 < K; k0 += 32) {
        #pragma unroll
        for (int i = 0; i < 4; i++) {
            uint4 ua = make_uint4(f2tf32(ra[i].x), f2tf32(ra[i].y),
                                  f2tf32(ra[i].z), f2tf32(ra[i].w));
            uint4 ub = make_uint4(f2tf32(rb[i].x), f2tf32(rb[i].y),
                                  f2tf32(rb[i].z), f2tf32(rb[i].w));
            *(uint4*)&As[grow + i * 32][gq * 4] = ua;
            *(uint4*)&Bs[grow + i * 32][gq * 4] = ub;
        }
        __syncthreads();

        if (k0 + 32 < K) {
            #pragma unroll
            for (int i = 0; i < 4; i++) {
                ra[i] = *(const float4*)(Abase + (size_t)(i * 32) * K + k0 + 32);
                rb[i] = *(const float4*)(Wbase + (size_t)(i * 32) * K + k0 + 32);
            }
        }

        #pragma unroll
        for (int k8 = 0; k8 < 4; k8++) {
            uint32_t af[4][4], bf[4][2];
            #pragma unroll
            for (int mi = 0; mi < 4; mi++) {
                const float* p = &As[wm + mi * 16 + g][k8 * 8 + th];
                af[mi][0] = __float_as_uint(p[0]);
                af[mi][1] = __float_as_uint(p[8 * GPAD]);
                af[mi][2] = __float_as_uint(p[4]);
                af[mi][3] = __float_as_uint(p[8 * GPAD + 4]);
            }
            #pragma unroll
            for (int ni = 0; ni < 4; ni++) {
                const float* p = &Bs[wn + ni * 8 + g][k8 * 8 + th];
                bf[ni][0] = __float_as_uint(p[0]);
                bf[ni][1] = __float_as_uint(p[4]);
            }
            #pragma unroll
            for (int mi = 0; mi < 4; mi++)
                #pragma unroll
                for (int ni = 0; ni < 4; ni++)
                    mma_tf32(acc[mi][ni], af[mi], bf[ni]);
        }
        __syncthreads();
    }

    #pragma unroll
    for (int mi = 0; mi < 4; mi++) {
        #pragma unroll
        for (int ni = 0; ni < 4; ni++) {
            const int n  = n0 + wn + ni * 8 + th * 2;
            const float2 bv = *(const float2*)(bias + n);
            const int mA = m0 + wm + mi * 16 + g;
            const int mB = mA + 8;
            float2 vA, vB;
            vA.x = (acc[mi][ni][0] + bv.x) * scale;
            vA.y = (acc[mi][ni][1] + bv.y) * scale;
            vB.x = (acc[mi][ni][2] + bv.x) * scale;
            vB.y = (acc[mi][ni][3] + bv.y) * scale;
            if (MODE == 0) {
                *(float2*)(C + (size_t)mA * N + n) = vA;
                *(float2*)(C + (size_t)mB * N + n) = vB;
            } else {
                const int h = n >> 6;
                const int d = n & (DEPTH - 1);
                {
                    const int b = mA >> 11, s = mA & (SEQ - 1);
                    *(float2*)(C + (((size_t)(b * NHEAD + h)) * SEQ + s) * DEPTH + d) = vA;
                }
                {
                    const int b = mB >> 11, s = mB & (SEQ - 1);
                    *(float2*)(C + (((size_t)(b * NHEAD + h)) * SEQ + s) * DEPTH + d) = vB;
                }
            }
        }
    }
}

// ---------------------------------------------------------------------------
// Tensor-core flash attention (causal).
//   Br=128 queries per CTA (8 warps x 16 rows), Bc=64 keys per tile.
//   S = Q K^T via tf32x2 (3 MMAs: qh*kh + ql*kh + qh*kl)  -> ~fp32 logits.
//   O += P V via plain tf32 (P, V rounded once).
//   Q pre-scaled by 1/sqrt(64) in the projection.
// Fragment maps (m16n8k8, lane = 4*g + th):
//   A: a0=A[g][th]   a1=A[g+8][th]   a2=A[g][th+4]   a3=A[g+8][th+4]
//   B: b0=B[th][n=g] b1=B[th+4][g]
//   C: c0=C[g][2th]  c1=C[g][2th+1]  c2=C[g+8][2th]  c3=C[g+8][2th+1]
// ---------------------------------------------------------------------------
#define KPITCH 68   // 68 % 32 == 4  -> b-frag LDS bank = lane (conflict-free)
#define VPITCH 72   // 72 % 32 == 8  -> b-frag LDS bank = 8*th+g (conflict-free)
#define PPITCH 68

#define ATT_SMEM_FLOATS (2 * 64 * KPITCH + 64 * VPITCH + 128 * PPITCH)

extern __shared__ float att_smem[];

__global__ void __launch_bounds__(256, 1)
attn_mma_kernel(const float* __restrict__ Q,
                const float* __restrict__ K,
                const float* __restrict__ V,
                float* __restrict__ ctx)
{
    float* skh = att_smem;                    // [64][KPITCH] K hi (tf32 bits)
    float* skl = skh + 64 * KPITCH;           // [64][KPITCH] K lo
    float* sv  = skl + 64 * KPITCH;           // [64][VPITCH] V (tf32 bits)
    float* sp  = sv  + 64 * VPITCH;           // [128][PPITCH] P (tf32 bits)

    const int tid  = threadIdx.x;
    const int warp = tid >> 5;
    const int lane = tid & 31;
    const int g    = lane >> 2;
    const int th   = lane & 3;

    const int bh   = blockIdx.x;              // head-major: bh fastest -> balanced waves
    const int qidx = blockIdx.y;
    const int q0   = qidx * 128;
    const int wr   = warp * 16;               // CTA-local row base of this warp

    const float* Qb = Q + ((size_t)bh * SEQ + q0 + wr) * DEPTH;
    const float* Kb = K + (size_t)bh * SEQ * DEPTH;
    const float* Vb = V + (size_t)bh * SEQ * DEPTH;

    // ---- Q fragments, hi+lo, loaded once (rows g, g+8 of warp block) ----
    uint32_t qhi[8][4], qlo[8][4];
    #pragma unroll
    for (int j = 0; j < 8; j++) {
        float x[4];
        x[0] = Qb[(size_t)g       * DEPTH + j * 8 + th];
        x[1] = Qb[(size_t)(g + 8) * DEPTH + j * 8 + th];
        x[2] = Qb[(size_t)g       * DEPTH + j * 8 + th + 4];
        x[3] = Qb[(size_t)(g + 8) * DEPTH + j * 8 + th + 4];
        #pragma unroll
        for (int r = 0; r < 4; r++) {
            uint32_t h = f2tf32(x[r]);
            qhi[j][r] = h;
            qlo[j][r] = f2tf32(x[r] - __uint_as_float(h));
        }
    }

    float acc[8][4];
    #pragma unroll
    for (int n = 0; n < 8; n++)
        #pragma unroll
        for (int r = 0; r < 4; r++) acc[n][r] = 0.0f;

    float mA = -1e30f, mB = -1e30f, lA = 0.0f, lB = 0.0f;

    const int nkt = 2 * qidx + 2;
    for (int kt = 0; kt < nkt; kt++) {
        const int k0 = kt * 64;
        __syncthreads();
        // ---- cooperative K/V tile load + tf32 conversion ----
        #pragma unroll
        for (int i = 0; i < 4; i++) {
            int f   = tid + i * 256;
            int row = f >> 4;
            int c4  = f & 15;
            float4 kx = *(const float4*)(Kb + (size_t)(k0 + row) * DEPTH + c4 * 4);
            float4 vx = *(const float4*)(Vb + (size_t)(k0 + row) * DEPTH + c4 * 4);
            uint4 h, l;
            h.x = f2tf32(kx.x); l.x = f2tf32(kx.x - __uint_as_float(h.x));
            h.y = f2tf32(kx.y); l.y = f2tf32(kx.y - __uint_as_float(h.y));
            h.z = f2tf32(kx.z); l.z = f2tf32(kx.z - __uint_as_float(h.z));
            h.w = f2tf32(kx.w); l.w = f2tf32(kx.w - __uint_as_float(h.w));
            *(uint4*)&skh[row * KPITCH + c4 * 4] = h;
            *(uint4*)&skl[row * KPITCH + c4 * 4] = l;
            uint4 vq = make_uint4(f2tf32(vx.x), f2tf32(vx.y),
                                  f2tf32(vx.z), f2tf32(vx.w));
            *(uint4*)&sv[row * VPITCH + c4 * 4] = vq;
        }
        __syncthreads();

        // ---- S = Q K^T  (tf32x2) ----
        float s[8][4];
        #pragma unroll
        for (int n = 0; n < 8; n++)
            #pragma unroll
            for (int r = 0; r < 4; r++) s[n][r] = 0.0f;

        #pragma unroll
        for (int k = 0; k < 8; k++) {
            #pragma unroll
            for (int n = 0; n < 8; n++) {
                const float* hp = &skh[(n * 8 + g) * KPITCH + k * 8 + th];
                const float* lp = &skl[(n * 8 + g) * KPITCH + k * 8 + th];
                uint32_t bhf[2] = { __float_as_uint(hp[0]), __float_as_uint(hp[4]) };
                uint32_t blf[2] = { __float_as_uint(lp[0]), __float_as_uint(lp[4]) };
                mma_tf32(s[n], qhi[k], bhf);
                mma_tf32(s[n], qlo[k], bhf);
                mma_tf32(s[n], qhi[k], blf);
            }
        }

        // ---- causal mask (only tiles that can touch the diagonal) ----
        const int rA = q0 + wr + g;
        const int rB = rA + 8;
        if (k0 + 63 > q0 + wr) {
            #pragma unroll
            for (int n = 0; n < 8; n++) {
                const int c = k0 + n * 8 + 2 * th;
                if (c     > rA) s[n][0] = -1e30f;
                if (c + 1 > rA) s[n][1] = -1e30f;
                if (c     > rB) s[n][2] = -1e30f;
                if (c + 1 > rB) s[n][3] = -1e30f;
            }
        }

        // ---- online softmax (rows g and g+8; quad holds all 64 cols) ----
        float rmA = -1e30f, rmB = -1e30f;
        #pragma unroll
        for (int n = 0; n < 8; n++) {
            rmA = fmaxf(rmA, fmaxf(s[n][0], s[n][1]));
            rmB = fmaxf(rmB, fmaxf(s[n][2], s[n][3]));
        }
        rmA = fmaxf(rmA, __shfl_xor_sync(0xffffffffu, rmA, 1));
        rmA = fmaxf(rmA, __shfl_xor_sync(0xffffffffu, rmA, 2));
        rmB = fmaxf(rmB, __shfl_xor_sync(0xffffffffu, rmB, 1));
        rmB = fmaxf(rmB, __shfl_xor_sync(0xffffffffu, rmB, 2));

        const float mnA = fmaxf(mA, rmA);
        const float mnB = fmaxf(mB, rmB);
        const float aA  = __expf(mA - mnA);
        const float aB  = __expf(mB - mnB);
        mA = mnA; mB = mnB;

        float sumA = 0.0f, sumB = 0.0f;
        #pragma unroll
        for (int n = 0; n < 8; n++) {
            s[n][0] = __expf(s[n][0] - mnA); sumA += s[n][0];
            s[n][1] = __expf(s[n][1] - mnA); sumA += s[n][1];
            s[n][2] = __expf(s[n][2] - mnB); sumB += s[n][2];
            s[n][3] = __expf(s[n][3] - mnB); sumB += s[n][3];
        }
        sumA += __shfl_xor_sync(0xffffffffu, sumA, 1);
        sumA += __shfl_xor_sync(0xffffffffu, sumA, 2);
        sumB += __shfl_xor_sync(0xffffffffu, sumB, 1);
        sumB += __shfl_xor_sync(0xffffffffu, sumB, 2);
        lA = lA * aA + sumA;
        lB = lB * aB + sumB;

        #pragma unroll
        for (int n = 0; n < 8; n++) {
            acc[n][0] *= aA; acc[n][1] *= aA;
            acc[n][2] *= aB; acc[n][3] *= aB;
        }

        // ---- P -> smem (tf32 bits); rows are warp-private ----
        #pragma unroll
        for (int n = 0; n < 8; n++) {
            uint2 pA = make_uint2(f2tf32(s[n][0]), f2tf32(s[n][1]));
            uint2 pB = make_uint2(f2tf32(s[n][2]), f2tf32(s[n][3]));
            *(uint2*)&sp[(wr + g    ) * PPITCH + n * 8 + 2 * th] = pA;
            *(uint2*)&sp[(wr + g + 8) * PPITCH + n * 8 + 2 * th] = pB;
        }
        __syncwarp();

        // ---- O += P V  (plain tf32) ----
        #pragma unroll
        for (int k = 0; k < 8; k++) {
            uint32_t pa[4];
            const float* p0 = &sp[(wr + g    ) * PPITCH + k * 8 + th];
            const float* p8 = &sp[(wr + g + 8) * PPITCH + k * 8 + th];
            pa[0] = __float_as_uint(p0[0]);
            pa[1] = __float_as_uint(p8[0]);
            pa[2] = __float_as_uint(p0[4]);
            pa[3] = __float_as_uint(p8[4]);
            #pragma unroll
            for (int n = 0; n < 8; n++) {
                const float* vp = &sv[(k * 8 + th) * VPITCH + n * 8 + g];
                uint32_t vb[2] = { __float_as_uint(vp[0]),
                                   __float_as_uint(vp[4 * VPITCH]) };
                mma_tf32(acc[n], pa, vb);
            }
        }
    }

    // ---- finalize -> ctx token-major [B,S,1024] ----
    const float iA = 1.0f / lA;
    const float iB = 1.0f / lB;
    const int b = bh >> 4;
    const int h = bh & 15;
    const size_t rowA = (size_t)b * SEQ + q0 + wr + g;
    const size_t rowB = rowA + 8;
    #pragma unroll
    for (int n = 0; n < 8; n++) {
        const int d = h * DEPTH + n * 8 + 2 * th;
        float2 oA = make_float2(acc[n][0] * iA, acc[n][1] * iA);
        float2 oB = make_float2(acc[n][2] * iB, acc[n][3] * iB);
        *(float2*)(ctx + rowA * DMODEL + d) = oA;
        *(float2*)(ctx + rowB * DMODEL + d) = oB;
    }
}

// ---------------------------------------------------------------------------
// Launch
// ---------------------------------------------------------------------------
extern "C" void kernel_launch(void* const* d_in, const int* in_sizes, int n_in,
                              void* d_out, int out_size)
{
    const float* q       = (const float*)d_in[0];
    const float* k       = (const float*)d_in[1];
    const float* v       = (const float*)d_in[2];
    const float* wq_w    = (const float*)d_in[3];
    const float* wq_b    = (const float*)d_in[4];
    const float* wk_w    = (const float*)d_in[5];
    const float* wk_b    = (const float*)d_in[6];
    const float* wv_w    = (const float*)d_in[7];
    const float* wv_b    = (const float*)d_in[8];
    const float* dense_w = (const float*)d_in[9];
    const float* dense_b = (const float*)d_in[10];
    float* out           = (float*)d_out;

    float *qh, *kh, *vh, *ctx;
    cudaGetSymbolAddress((void**)&qh,  g_qh);
    cudaGetSymbolAddress((void**)&kh,  g_kh);
    cudaGetSymbolAddress((void**)&vh,  g_vh);
    cudaGetSymbolAddress((void**)&ctx, g_ctx);

    const dim3 ggrid(DMODEL / 128, NTOK / 128);   // (8, 64)
    const dim3 gblk(256);

    // Projections -> head-major; fold softmax scale into Q.
    gemm_tf32_kernel<1><<<ggrid, gblk>>>(q, wq_w, wq_b, qh, NTOK, DMODEL, DMODEL, QK_SCALE);
    gemm_tf32_kernel<1><<<ggrid, gblk>>>(k, wk_w, wk_b, kh, NTOK, DMODEL, DMODEL, 1.0f);
    gemm_tf32_kernel<1><<<ggrid, gblk>>>(v, wv_w, wv_b, vh, NTOK, DMODEL, DMODEL, 1.0f);

    // Tensor-core flash attention
    const int att_smem_bytes = ATT_SMEM_FLOATS * (int)sizeof(float);  // 88064
    cudaFuncSetAttribute(attn_mma_kernel, cudaFuncAttributeMaxDynamicSharedMemorySize,
                         att_smem_bytes);
    dim3 agrid(BATCH * NHEAD, SEQ / 128);         // (64, 16), bh fastest
    attn_mma_kernel<<<agrid, 256, att_smem_bytes>>>(qh, kh, vh, ctx);

    // Output dense
    gemm_tf32_kernel<0><<<ggrid, gblk>>>(ctx, dense_w, dense_b, out, NTOK, DMODEL, DMODEL, 1.0f);
}

// round 10
// speedup vs baseline: 3.6818x; 1.0434x over previous
#include <cuda_runtime.h>
#include <cuda_bf16.h>
#include <cstdint>

// Problem constants
#define BATCH     4
#define SEQ       2048
#define DMODEL    1024
#define NHEAD     16
#define DEPTH     64
#define NTOK      (BATCH * SEQ)          // 8192
#define QK_SCALE  0.125f                 // 1/sqrt(64)

// ---------------------------------------------------------------------------
// Scratch buffers (allocations are forbidden; __device__ globals are allowed)
// ---------------------------------------------------------------------------
__device__ float g_qh [NTOK * DMODEL];   // [B,H,S,64] head-major, pre-scaled
__device__ float g_kh [NTOK * DMODEL];   // [B,H,S,64]
__device__ float g_vh [NTOK * DMODEL];   // [B,H,S,64]
__device__ float g_ctx[NTOK * DMODEL];   // [B,S,1024] token-major

// ---------------------------------------------------------------------------
// TF32 helpers
// ---------------------------------------------------------------------------
__device__ __forceinline__ uint32_t f2tf32(float x) {
    uint32_t r;
    asm("cvt.rna.tf32.f32 %0, %1;" : "=r"(r) : "f"(x));
    return r;
}

__device__ __forceinline__ void mma_tf32(float d[4],
                                         const uint32_t a[4],
                                         const uint32_t b[2]) {
    asm volatile(
        "mma.sync.aligned.m16n8k8.row.col.f32.tf32.tf32.f32 "
        "{%0,%1,%2,%3}, {%4,%5,%6,%7}, {%8,%9}, {%0,%1,%2,%3};\n"
        : "+f"(d[0]), "+f"(d[1]), "+f"(d[2]), "+f"(d[3])
        : "r"(a[0]), "r"(a[1]), "r"(a[2]), "r"(a[3]),
          "r"(b[0]), "r"(b[1]));
}

// ---------------------------------------------------------------------------
// TF32 GEMM: C = (A[M,K] @ W[N,K]^T + bias) * scale   (proven, unchanged)
// ---------------------------------------------------------------------------
#define GPAD 36

template <int MODE>
__global__ void __launch_bounds__(256, 2)
gemm_tf32_kernel(const float* __restrict__ A,
                 const float* __restrict__ W,
                 const float* __restrict__ bias,
                 float* __restrict__ C,
                 int M, int N, int K, float scale)
{
    __shared__ float As[128][GPAD];
    __shared__ float Bs[128][GPAD];

    const int tid  = threadIdx.x;
    const int warp = tid >> 5;
    const int lane = tid & 31;
    const int wm   = (warp >> 2) * 64;
    const int wn   = (warp & 3) * 32;
    const int g    = lane >> 2;
    const int th   = lane & 3;
    const int m0   = blockIdx.y * 128;
    const int n0   = blockIdx.x * 128;

    float acc[4][4][4];
    #pragma unroll
    for (int mi = 0; mi < 4; mi++)
        #pragma unroll
        for (int ni = 0; ni < 4; ni++)
            #pragma unroll
            for (int r = 0; r < 4; r++) acc[mi][ni][r] = 0.0f;

    const int grow = tid >> 3;
    const int gq   = tid & 7;
    const float* Abase = A + (size_t)(m0 + grow) * K + gq * 4;
    const float* Wbase = W + (size_t)(n0 + grow) * K + gq * 4;

    float4 ra[4], rb[4];
    #pragma unroll
    for (int i = 0; i < 4; i++) {
        ra[i] = *(const float4*)(Abase + (size_t)(i * 32) * K);
        rb[i] = *(const float4*)(Wbase + (size_t)(i * 32) * K);
    }

    for (int k0 = 0; k0 < K; k0 += 32) {
        #pragma unroll
        for (int i = 0; i < 4; i++) {
            uint4 ua = make_uint4(f2tf32(ra[i].x), f2tf32(ra[i].y),
                                  f2tf32(ra[i].z), f2tf32(ra[i].w));
            uint4 ub = make_uint4(f2tf32(rb[i].x), f2tf32(rb[i].y),
                                  f2tf32(rb[i].z), f2tf32(rb[i].w));
            *(uint4*)&As[grow + i * 32][gq * 4] = ua;
            *(uint4*)&Bs[grow + i * 32][gq * 4] = ub;
        }
        __syncthreads();

        if (k0 + 32 < K) {
            #pragma unroll
            for (int i = 0; i < 4; i++) {
                ra[i] = *(const float4*)(Abase + (size_t)(i * 32) * K + k0 + 32);
                rb[i] = *(const float4*)(Wbase + (size_t)(i * 32) * K + k0 + 32);
            }
        }

        #pragma unroll
        for (int k8 = 0; k8 < 4; k8++) {
            uint32_t af[4][4], bf[4][2];
            #pragma unroll
            for (int mi = 0; mi < 4; mi++) {
                const float* p = &As[wm + mi * 16 + g][k8 * 8 + th];
                af[mi][0] = __float_as_uint(p[0]);
                af[mi][1] = __float_as_uint(p[8 * GPAD]);
                af[mi][2] = __float_as_uint(p[4]);
                af[mi][3] = __float_as_uint(p[8 * GPAD + 4]);
            }
            #pragma unroll
            for (int ni = 0; ni < 4; ni++) {
                const float* p = &Bs[wn + ni * 8 + g][k8 * 8 + th];
                bf[ni][0] = __float_as_uint(p[0]);
                bf[ni][1] = __float_as_uint(p[4]);
            }
            #pragma unroll
            for (int mi = 0; mi < 4; mi++)
                #pragma unroll
                for (int ni = 0; ni < 4; ni++)
                    mma_tf32(acc[mi][ni], af[mi], bf[ni]);
        }
        __syncthreads();
    }

    #pragma unroll
    for (int mi = 0; mi < 4; mi++) {
        #pragma unroll
        for (int ni = 0; ni < 4; ni++) {
            const int n  = n0 + wn + ni * 8 + th * 2;
            const float2 bv = *(const float2*)(bias + n);
            const int mA = m0 + wm + mi * 16 + g;
            const int mB = mA + 8;
            float2 vA, vB;
            vA.x = (acc[mi][ni][0] + bv.x) * scale;
            vA.y = (acc[mi][ni][1] + bv.y) * scale;
            vB.x = (acc[mi][ni][2] + bv.x) * scale;
            vB.y = (acc[mi][ni][3] + bv.y) * scale;
            if (MODE == 0) {
                *(float2*)(C + (size_t)mA * N + n) = vA;
                *(float2*)(C + (size_t)mB * N + n) = vB;
            } else {
                const int h = n >> 6;
                const int d = n & (DEPTH - 1);
                {
                    const int b = mA >> 11, s = mA & (SEQ - 1);
                    *(float2*)(C + (((size_t)(b * NHEAD + h)) * SEQ + s) * DEPTH + d) = vA;
                }
                {
                    const int b = mB >> 11, s = mB & (SEQ - 1);
                    *(float2*)(C + (((size_t)(b * NHEAD + h)) * SEQ + s) * DEPTH + d) = vB;
                }
            }
        }
    }
}

// ---------------------------------------------------------------------------
// Tensor-core flash attention (causal), software-pipelined.
//   Br=128 queries per CTA (8 warps x 16 rows), Bc=64 keys per tile.
//   S = Q K^T via tf32x2 (3 MMAs), O += P V via plain tf32.
//   Double-buffered K/V smem tiles + register prefetch: ONE barrier per tile,
//   global loads for tile kt+1 overlap the compute of tile kt.
// ---------------------------------------------------------------------------
#define KPITCH 68   // 68 % 32 == 4  -> b-frag LDS bank = lane (conflict-free)
#define VPITCH 72   // 72 % 32 == 8  -> b-frag LDS bank = 8*th+g (conflict-free)
#define PPITCH 68

#define KVBUF   (2 * 64 * KPITCH + 64 * VPITCH)          // one K/V buffer: 13312
#define ATT_SMEM_FLOATS (2 * KVBUF + 128 * PPITCH)       // 35328 fl = 141312 B

extern __shared__ float att_smem[];

__global__ void __launch_bounds__(256, 1)
attn_mma_kernel(const float* __restrict__ Q,
                const float* __restrict__ K,
                const float* __restrict__ V,
                float* __restrict__ ctx)
{
    float* sp = att_smem + 2 * KVBUF;         // [128][PPITCH] P (tf32 bits)

    const int tid  = threadIdx.x;
    const int warp = tid >> 5;
    const int lane = tid & 31;
    const int g    = lane >> 2;
    const int th   = lane & 3;

    const int bh   = blockIdx.x;              // head-major: balanced waves
    const int qidx = blockIdx.y;
    const int q0   = qidx * 128;
    const int wr   = warp * 16;               // CTA-local row base of this warp

    const float* Qb = Q + ((size_t)bh * SEQ + q0 + wr) * DEPTH;
    const float* Kb = K + (size_t)bh * SEQ * DEPTH;
    const float* Vb = V + (size_t)bh * SEQ * DEPTH;

    // per-thread gmem load mapping (row, col4) for 64x64 tiles
    const int lrow = tid >> 4;                // 0..15, +16 per i
    const int lc4  = tid & 15;

    // ---- Q fragments, hi+lo, loaded once (rows g, g+8 of warp block) ----
    uint32_t qhi[8][4], qlo[8][4];
    #pragma unroll
    for (int j = 0; j < 8; j++) {
        float x[4];
        x[0] = Qb[(size_t)g       * DEPTH + j * 8 + th];
        x[1] = Qb[(size_t)(g + 8) * DEPTH + j * 8 + th];
        x[2] = Qb[(size_t)g       * DEPTH + j * 8 + th + 4];
        x[3] = Qb[(size_t)(g + 8) * DEPTH + j * 8 + th + 4];
        #pragma unroll
        for (int r = 0; r < 4; r++) {
            uint32_t h = f2tf32(x[r]);
            qhi[j][r] = h;
            qlo[j][r] = f2tf32(x[r] - __uint_as_float(h));
        }
    }

    float acc[8][4];
    #pragma unroll
    for (int n = 0; n < 8; n++)
        #pragma unroll
        for (int r = 0; r < 4; r++) acc[n][r] = 0.0f;

    float mA = -1e30f, mB = -1e30f, lA = 0.0f, lB = 0.0f;

    const int nkt = 2 * qidx + 2;

    // ---- preload tile 0 into registers ----
    float4 kx[4], vx[4];
    #pragma unroll
    for (int i = 0; i < 4; i++) {
        kx[i] = *(const float4*)(Kb + (size_t)(lrow + i * 16) * DEPTH + lc4 * 4);
        vx[i] = *(const float4*)(Vb + (size_t)(lrow + i * 16) * DEPTH + lc4 * 4);
    }

    for (int kt = 0; kt < nkt; kt++) {
        const int k0 = kt * 64;
        float* skh = att_smem + (kt & 1) * KVBUF;   // [64][KPITCH]
        float* skl = skh + 64 * KPITCH;             // [64][KPITCH]
        float* sv  = skl + 64 * KPITCH;             // [64][VPITCH]

        // ---- store prefetched regs -> buf[kt&1], tf32 hi/lo ----
        // (barrier of iteration kt-1 guarantees all warps finished reading
        //  this buffer at iteration kt-2)
        #pragma unroll
        for (int i = 0; i < 4; i++) {
            const int row = lrow + i * 16;
            uint4 h, l;
            h.x = f2tf32(kx[i].x); l.x = f2tf32(kx[i].x - __uint_as_float(h.x));
            h.y = f2tf32(kx[i].y); l.y = f2tf32(kx[i].y - __uint_as_float(h.y));
            h.z = f2tf32(kx[i].z); l.z = f2tf32(kx[i].z - __uint_as_float(h.z));
            h.w = f2tf32(kx[i].w); l.w = f2tf32(kx[i].w - __uint_as_float(h.w));
            *(uint4*)&skh[row * KPITCH + lc4 * 4] = h;
            *(uint4*)&skl[row * KPITCH + lc4 * 4] = l;
            uint4 vq = make_uint4(f2tf32(vx[i].x), f2tf32(vx[i].y),
                                  f2tf32(vx[i].z), f2tf32(vx[i].w));
            *(uint4*)&sv[row * VPITCH + lc4 * 4] = vq;
        }
        __syncthreads();

        // ---- issue global loads for tile kt+1 (overlap with compute) ----
        if (kt + 1 < nkt) {
            const float* Kn = Kb + (size_t)(k0 + 64) * DEPTH;
            const float* Vn = Vb + (size_t)(k0 + 64) * DEPTH;
            #pragma unroll
            for (int i = 0; i < 4; i++) {
                kx[i] = *(const float4*)(Kn + (size_t)(lrow + i * 16) * DEPTH + lc4 * 4);
                vx[i] = *(const float4*)(Vn + (size_t)(lrow + i * 16) * DEPTH + lc4 * 4);
            }
        }

        // ---- S = Q K^T  (tf32x2) ----
        float s[8][4];
        #pragma unroll
        for (int n = 0; n < 8; n++)
            #pragma unroll
            for (int r = 0; r < 4; r++) s[n][r] = 0.0f;

        #pragma unroll
        for (int k = 0; k < 8; k++) {
            #pragma unroll
            for (int n = 0; n < 8; n++) {
                const float* hp = &skh[(n * 8 + g) * KPITCH + k * 8 + th];
                const float* lp = &skl[(n * 8 + g) * KPITCH + k * 8 + th];
                uint32_t bhf[2] = { __float_as_uint(hp[0]), __float_as_uint(hp[4]) };
                uint32_t blf[2] = { __float_as_uint(lp[0]), __float_as_uint(lp[4]) };
                mma_tf32(s[n], qhi[k], bhf);
                mma_tf32(s[n], qlo[k], bhf);
                mma_tf32(s[n], qhi[k], blf);
            }
        }

        // ---- causal mask (only tiles that can touch the diagonal) ----
        const int rA = q0 + wr + g;
        const int rB = rA + 8;
        if (k0 + 63 > q0 + wr) {
            #pragma unroll
            for (int n = 0; n < 8; n++) {
                const int c = k0 + n * 8 + 2 * th;
                if (c     > rA) s[n][0] = -1e30f;
                if (c + 1 > rA) s[n][1] = -1e30f;
                if (c     > rB) s[n][2] = -1e30f;
                if (c + 1 > rB) s[n][3] = -1e30f;
            }
        }

        // ---- online softmax (rows g and g+8; quad holds all 64 cols) ----
        float rmA = -1e30f, rmB = -1e30f;
        #pragma unroll
        for (int n = 0; n < 8; n++) {
            rmA = fmaxf(rmA, fmaxf(s[n][0], s[n][1]));
            rmB = fmaxf(rmB, fmaxf(s[n][2], s[n][3]));
        }
        rmA = fmaxf(rmA, __shfl_xor_sync(0xffffffffu, rmA, 1));
        rmA = fmaxf(rmA, __shfl_xor_sync(0xffffffffu, rmA, 2));
        rmB = fmaxf(rmB, __shfl_xor_sync(0xffffffffu, rmB, 1));
        rmB = fmaxf(rmB, __shfl_xor_sync(0xffffffffu, rmB, 2));

        const float mnA = fmaxf(mA, rmA);
        const float mnB = fmaxf(mB, rmB);
        const float aA  = __expf(mA - mnA);
        const float aB  = __expf(mB - mnB);
        mA = mnA; mB = mnB;

        float sumA = 0.0f, sumB = 0.0f;
        #pragma unroll
        for (int n = 0; n < 8; n++) {
            s[n][0] = __expf(s[n][0] - mnA); sumA += s[n][0];
            s[n][1] = __expf(s[n][1] - mnA); sumA += s[n][1];
            s[n][2] = __expf(s[n][2] - mnB); sumB += s[n][2];
            s[n][3] = __expf(s[n][3] - mnB); sumB += s[n][3];
        }
        sumA += __shfl_xor_sync(0xffffffffu, sumA, 1);
        sumA += __shfl_xor_sync(0xffffffffu, sumA, 2);
        sumB += __shfl_xor_sync(0xffffffffu, sumB, 1);
        sumB += __shfl_xor_sync(0xffffffffu, sumB, 2);
        lA = lA * aA + sumA;
        lB = lB * aB + sumB;

        #pragma unroll
        for (int n = 0; n < 8; n++) {
            acc[n][0] *= aA; acc[n][1] *= aA;
            acc[n][2] *= aB; acc[n][3] *= aB;
        }

        // ---- P -> smem (tf32 bits); rows are warp-private ----
        #pragma unroll
        for (int n = 0; n < 8; n++) {
            uint2 pA = make_uint2(f2tf32(s[n][0]), f2tf32(s[n][1]));
            uint2 pB = make_uint2(f2tf32(s[n][2]), f2tf32(s[n][3]));
            *(uint2*)&sp[(wr + g    ) * PPITCH + n * 8 + 2 * th] = pA;
            *(uint2*)&sp[(wr + g + 8) * PPITCH + n * 8 + 2 * th] = pB;
        }
        __syncwarp();

        // ---- O += P V  (plain tf32) ----
        #pragma unroll
        for (int k = 0; k < 8; k++) {
            uint32_t pa[4];
            const float* p0 = &sp[(wr + g    ) * PPITCH + k * 8 + th];
            const float* p8 = &sp[(wr + g + 8) * PPITCH + k * 8 + th];
            pa[0] = __float_as_uint(p0[0]);
            pa[1] = __float_as_uint(p8[0]);
            pa[2] = __float_as_uint(p0[4]);
            pa[3] = __float_as_uint(p8[4]);
            #pragma unroll
            for (int n = 0; n < 8; n++) {
                const float* vp = &sv[(k * 8 + th) * VPITCH + n * 8 + g];
                uint32_t vb[2] = { __float_as_uint(vp[0]),
                                   __float_as_uint(vp[4 * VPITCH]) };
                mma_tf32(acc[n], pa, vb);
            }
        }
    }

    // ---- finalize -> ctx token-major [B,S,1024] ----
    const float iA = 1.0f / lA;
    const float iB = 1.0f / lB;
    const int b = bh >> 4;
    const int h = bh & 15;
    const size_t rowA = (size_t)b * SEQ + q0 + wr + g;
    const size_t rowB = rowA + 8;
    #pragma unroll
    for (int n = 0; n < 8; n++) {
        const int d = h * DEPTH + n * 8 + 2 * th;
        float2 oA = make_float2(acc[n][0] * iA, acc[n][1] * iA);
        float2 oB = make_float2(acc[n][2] * iB, acc[n][3] * iB);
        *(float2*)(ctx + rowA * DMODEL + d) = oA;
        *(float2*)(ctx + rowB * DMODEL + d) = oB;
    }
}

// ---------------------------------------------------------------------------
// Launch
// ---------------------------------------------------------------------------
extern "C" void kernel_launch(void* const* d_in, const int* in_sizes, int n_in,
                              void* d_out, int out_size)
{
    const float* q       = (const float*)d_in[0];
    const float* k       = (const float*)d_in[1];
    const float* v       = (const float*)d_in[2];
    const float* wq_w    = (const float*)d_in[3];
    const float* wq_b    = (const float*)d_in[4];
    const float* wk_w    = (const float*)d_in[5];
    const float* wk_b    = (const float*)d_in[6];
    const float* wv_w    = (const float*)d_in[7];
    const float* wv_b    = (const float*)d_in[8];
    const float* dense_w = (const float*)d_in[9];
    const float* dense_b = (const float*)d_in[10];
    float* out           = (float*)d_out;

    float *qh, *kh, *vh, *ctx;
    cudaGetSymbolAddress((void**)&qh,  g_qh);
    cudaGetSymbolAddress((void**)&kh,  g_kh);
    cudaGetSymbolAddress((void**)&vh,  g_vh);
    cudaGetSymbolAddress((void**)&ctx, g_ctx);

    const dim3 ggrid(DMODEL / 128, NTOK / 128);   // (8, 64)
    const dim3 gblk(256);

    // Projections -> head-major; fold softmax scale into Q.
    gemm_tf32_kernel<1><<<ggrid, gblk>>>(q, wq_w, wq_b, qh, NTOK, DMODEL, DMODEL, QK_SCALE);
    gemm_tf32_kernel<1><<<ggrid, gblk>>>(k, wk_w, wk_b, kh, NTOK, DMODEL, DMODEL, 1.0f);
    gemm_tf32_kernel<1><<<ggrid, gblk>>>(v, wv_w, wv_b, vh, NTOK, DMODEL, DMODEL, 1.0f);

    // Tensor-core flash attention (pipelined)
    const int att_smem_bytes = ATT_SMEM_FLOATS * (int)sizeof(float);  // 141312
    cudaFuncSetAttribute(attn_mma_kernel, cudaFuncAttributeMaxDynamicSharedMemorySize,
                         att_smem_bytes);
    dim3 agrid(BATCH * NHEAD, SEQ / 128);         // (64, 16), bh fastest
    attn_mma_kernel<<<agrid, 256, att_smem_bytes>>>(qh, kh, vh, ctx);

    // Output dense
    gemm_tf32_kernel<0><<<ggrid, gblk>>>(ctx, dense_w, dense_b, out, NTOK, DMODEL, DMODEL, 1.0f);
}

// round 11
// speedup vs baseline: 4.0326x; 1.0953x over previous
#include <cuda_runtime.h>
#include <cuda_bf16.h>
#include <cstdint>

// Problem constants
#define BATCH     4
#define SEQ       2048
#define DMODEL    1024
#define NHEAD     16
#define DEPTH     64
#define NTOK      (BATCH * SEQ)          // 8192
#define QK_SCALE  0.125f                 // 1/sqrt(64)

// ---------------------------------------------------------------------------
// Scratch buffers (allocations are forbidden; __device__ globals are allowed)
// ---------------------------------------------------------------------------
__device__ float g_qh [NTOK * DMODEL];   // [B,H,S,64] head-major, pre-scaled
__device__ float g_kh [NTOK * DMODEL];   // [B,H,S,64]
__device__ float g_vh [NTOK * DMODEL];   // [B,H,S,64]
__device__ float g_ctx[NTOK * DMODEL];   // [B,S,1024] token-major

// ---------------------------------------------------------------------------
// TF32 helpers
// ---------------------------------------------------------------------------
__device__ __forceinline__ uint32_t f2tf32(float x) {
    uint32_t r;
    asm("cvt.rna.tf32.f32 %0, %1;" : "=r"(r) : "f"(x));
    return r;
}

__device__ __forceinline__ void mma_tf32(float d[4],
                                         const uint32_t a[4],
                                         const uint32_t b[2]) {
    asm volatile(
        "mma.sync.aligned.m16n8k8.row.col.f32.tf32.tf32.f32 "
        "{%0,%1,%2,%3}, {%4,%5,%6,%7}, {%8,%9}, {%0,%1,%2,%3};\n"
        : "+f"(d[0]), "+f"(d[1]), "+f"(d[2]), "+f"(d[3])
        : "r"(a[0]), "r"(a[1]), "r"(a[2]), "r"(a[3]),
          "r"(b[0]), "r"(b[1]));
}

// ---------------------------------------------------------------------------
// TF32 GEMM: C = (A[M,K] @ W[N,K]^T + bias) * scale   (proven, unchanged)
// ---------------------------------------------------------------------------
#define GPAD 36

template <int MODE>
__global__ void __launch_bounds__(256, 2)
gemm_tf32_kernel(const float* __restrict__ A,
                 const float* __restrict__ W,
                 const float* __restrict__ bias,
                 float* __restrict__ C,
                 int M, int N, int K, float scale)
{
    __shared__ float As[128][GPAD];
    __shared__ float Bs[128][GPAD];

    const int tid  = threadIdx.x;
    const int warp = tid >> 5;
    const int lane = tid & 31;
    const int wm   = (warp >> 2) * 64;
    const int wn   = (warp & 3) * 32;
    const int g    = lane >> 2;
    const int th   = lane & 3;
    const int m0   = blockIdx.y * 128;
    const int n0   = blockIdx.x * 128;

    float acc[4][4][4];
    #pragma unroll
    for (int mi = 0; mi < 4; mi++)
        #pragma unroll
        for (int ni = 0; ni < 4; ni++)
            #pragma unroll
            for (int r = 0; r < 4; r++) acc[mi][ni][r] = 0.0f;

    const int grow = tid >> 3;
    const int gq   = tid & 7;
    const float* Abase = A + (size_t)(m0 + grow) * K + gq * 4;
    const float* Wbase = W + (size_t)(n0 + grow) * K + gq * 4;

    float4 ra[4], rb[4];
    #pragma unroll
    for (int i = 0; i < 4; i++) {
        ra[i] = *(const float4*)(Abase + (size_t)(i * 32) * K);
        rb[i] = *(const float4*)(Wbase + (size_t)(i * 32) * K);
    }

    for (int k0 = 0; k0 < K; k0 += 32) {
        #pragma unroll
        for (int i = 0; i < 4; i++) {
            uint4 ua = make_uint4(f2tf32(ra[i].x), f2tf32(ra[i].y),
                                  f2tf32(ra[i].z), f2tf32(ra[i].w));
            uint4 ub = make_uint4(f2tf32(rb[i].x), f2tf32(rb[i].y),
                                  f2tf32(rb[i].z), f2tf32(rb[i].w));
            *(uint4*)&As[grow + i * 32][gq * 4] = ua;
            *(uint4*)&Bs[grow + i * 32][gq * 4] = ub;
        }
        __syncthreads();

        if (k0 + 32 < K) {
            #pragma unroll
            for (int i = 0; i < 4; i++) {
                ra[i] = *(const float4*)(Abase + (size_t)(i * 32) * K + k0 + 32);
                rb[i] = *(const float4*)(Wbase + (size_t)(i * 32) * K + k0 + 32);
            }
        }

        #pragma unroll
        for (int k8 = 0; k8 < 4; k8++) {
            uint32_t af[4][4], bf[4][2];
            #pragma unroll
            for (int mi = 0; mi < 4; mi++) {
                const float* p = &As[wm + mi * 16 + g][k8 * 8 + th];
                af[mi][0] = __float_as_uint(p[0]);
                af[mi][1] = __float_as_uint(p[8 * GPAD]);
                af[mi][2] = __float_as_uint(p[4]);
                af[mi][3] = __float_as_uint(p[8 * GPAD + 4]);
            }
            #pragma unroll
            for (int ni = 0; ni < 4; ni++) {
                const float* p = &Bs[wn + ni * 8 + g][k8 * 8 + th];
                bf[ni][0] = __float_as_uint(p[0]);
                bf[ni][1] = __float_as_uint(p[4]);
            }
            #pragma unroll
            for (int mi = 0; mi < 4; mi++)
                #pragma unroll
                for (int ni = 0; ni < 4; ni++)
                    mma_tf32(acc[mi][ni], af[mi], bf[ni]);
        }
        __syncthreads();
    }

    #pragma unroll
    for (int mi = 0; mi < 4; mi++) {
        #pragma unroll
        for (int ni = 0; ni < 4; ni++) {
            const int n  = n0 + wn + ni * 8 + th * 2;
            const float2 bv = *(const float2*)(bias + n);
            const int mA = m0 + wm + mi * 16 + g;
            const int mB = mA + 8;
            float2 vA, vB;
            vA.x = (acc[mi][ni][0] + bv.x) * scale;
            vA.y = (acc[mi][ni][1] + bv.y) * scale;
            vB.x = (acc[mi][ni][2] + bv.x) * scale;
            vB.y = (acc[mi][ni][3] + bv.y) * scale;
            if (MODE == 0) {
                *(float2*)(C + (size_t)mA * N + n) = vA;
                *(float2*)(C + (size_t)mB * N + n) = vB;
            } else {
                const int h = n >> 6;
                const int d = n & (DEPTH - 1);
                {
                    const int b = mA >> 11, s = mA & (SEQ - 1);
                    *(float2*)(C + (((size_t)(b * NHEAD + h)) * SEQ + s) * DEPTH + d) = vA;
                }
                {
                    const int b = mB >> 11, s = mB & (SEQ - 1);
                    *(float2*)(C + (((size_t)(b * NHEAD + h)) * SEQ + s) * DEPTH + d) = vB;
                }
            }
        }
    }
}

// ---------------------------------------------------------------------------
// Tensor-core flash attention (causal), software-pipelined.
//   Br=128 queries per CTA (8 warps x 16 rows), Bc=64 keys per tile.
//   S = Q K^T via 2 MMAs (qh*kh + ql*kh): Q error fully corrected, K carries
//   one tf32 rounding (~2.4e-4 on logits). O += P V via plain tf32.
//   Double-buffered K/V smem tiles + register prefetch: ONE barrier per tile.
// ---------------------------------------------------------------------------
#define KPITCH 68   // 68 % 32 == 4  -> b-frag LDS bank = lane (conflict-free)
#define VPITCH 72   // 72 % 32 == 8  -> b-frag LDS bank = 8*th+g (conflict-free)
#define PPITCH 68

#define KVBUF   (64 * KPITCH + 64 * VPITCH)              // one K/V buffer: 8960
#define ATT_SMEM_FLOATS (2 * KVBUF + 128 * PPITCH)       // 26624 fl = 106496 B

extern __shared__ float att_smem[];

__global__ void __launch_bounds__(256, 1)
attn_mma_kernel(const float* __restrict__ Q,
                const float* __restrict__ K,
                const float* __restrict__ V,
                float* __restrict__ ctx)
{
    float* sp = att_smem + 2 * KVBUF;         // [128][PPITCH] P (tf32 bits)

    const int tid  = threadIdx.x;
    const int warp = tid >> 5;
    const int lane = tid & 31;
    const int g    = lane >> 2;
    const int th   = lane & 3;

    const int bh   = blockIdx.x;              // head-major: balanced waves
    const int qidx = blockIdx.y;
    const int q0   = qidx * 128;
    const int wr   = warp * 16;               // CTA-local row base of this warp

    const float* Qb = Q + ((size_t)bh * SEQ + q0 + wr) * DEPTH;
    const float* Kb = K + (size_t)bh * SEQ * DEPTH;
    const float* Vb = V + (size_t)bh * SEQ * DEPTH;

    // per-thread gmem load mapping (row, col4) for 64x64 tiles
    const int lrow = tid >> 4;                // 0..15, +16 per i
    const int lc4  = tid & 15;

    // ---- Q fragments, hi+lo, loaded once (rows g, g+8 of warp block) ----
    uint32_t qhi[8][4], qlo[8][4];
    #pragma unroll
    for (int j = 0; j < 8; j++) {
        float x[4];
        x[0] = Qb[(size_t)g       * DEPTH + j * 8 + th];
        x[1] = Qb[(size_t)(g + 8) * DEPTH + j * 8 + th];
        x[2] = Qb[(size_t)g       * DEPTH + j * 8 + th + 4];
        x[3] = Qb[(size_t)(g + 8) * DEPTH + j * 8 + th + 4];
        #pragma unroll
        for (int r = 0; r < 4; r++) {
            uint32_t h = f2tf32(x[r]);
            qhi[j][r] = h;
            qlo[j][r] = f2tf32(x[r] - __uint_as_float(h));
        }
    }

    float acc[8][4];
    #pragma unroll
    for (int n = 0; n < 8; n++)
        #pragma unroll
        for (int r = 0; r < 4; r++) acc[n][r] = 0.0f;

    float mA = -1e30f, mB = -1e30f, lA = 0.0f, lB = 0.0f;

    const int nkt = 2 * qidx + 2;

    // ---- preload tile 0 into registers ----
    float4 kx[4], vx[4];
    #pragma unroll
    for (int i = 0; i < 4; i++) {
        kx[i] = *(const float4*)(Kb + (size_t)(lrow + i * 16) * DEPTH + lc4 * 4);
        vx[i] = *(const float4*)(Vb + (size_t)(lrow + i * 16) * DEPTH + lc4 * 4);
    }

    for (int kt = 0; kt < nkt; kt++) {
        const int k0 = kt * 64;
        float* skh = att_smem + (kt & 1) * KVBUF;   // [64][KPITCH] K (tf32)
        float* sv  = skh + 64 * KPITCH;             // [64][VPITCH] V (tf32)

        // ---- store prefetched regs -> buf[kt&1] (tf32) ----
        // (barrier of iteration kt-1 guarantees all warps finished reading
        //  this buffer at iteration kt-2)
        #pragma unroll
        for (int i = 0; i < 4; i++) {
            const int row = lrow + i * 16;
            uint4 h = make_uint4(f2tf32(kx[i].x), f2tf32(kx[i].y),
                                 f2tf32(kx[i].z), f2tf32(kx[i].w));
            *(uint4*)&skh[row * KPITCH + lc4 * 4] = h;
            uint4 vq = make_uint4(f2tf32(vx[i].x), f2tf32(vx[i].y),
                                  f2tf32(vx[i].z), f2tf32(vx[i].w));
            *(uint4*)&sv[row * VPITCH + lc4 * 4] = vq;
        }
        __syncthreads();

        // ---- issue global loads for tile kt+1 (overlap with compute) ----
        if (kt + 1 < nkt) {
            const float* Kn = Kb + (size_t)(k0 + 64) * DEPTH;
            const float* Vn = Vb + (size_t)(k0 + 64) * DEPTH;
            #pragma unroll
            for (int i = 0; i < 4; i++) {
                kx[i] = *(const float4*)(Kn + (size_t)(lrow + i * 16) * DEPTH + lc4 * 4);
                vx[i] = *(const float4*)(Vn + (size_t)(lrow + i * 16) * DEPTH + lc4 * 4);
            }
        }

        // ---- S = Q K^T  (2 MMAs: qh*kh + ql*kh) ----
        float s[8][4];
        #pragma unroll
        for (int n = 0; n < 8; n++)
            #pragma unroll
            for (int r = 0; r < 4; r++) s[n][r] = 0.0f;

        #pragma unroll
        for (int k = 0; k < 8; k++) {
            #pragma unroll
            for (int n = 0; n < 8; n++) {
                const float* hp = &skh[(n * 8 + g) * KPITCH + k * 8 + th];
                uint32_t bhf[2] = { __float_as_uint(hp[0]), __float_as_uint(hp[4]) };
                mma_tf32(s[n], qhi[k], bhf);
                mma_tf32(s[n], qlo[k], bhf);
            }
        }

        // ---- causal mask (only tiles that can touch the diagonal) ----
        const int rA = q0 + wr + g;
        const int rB = rA + 8;
        if (k0 + 63 > q0 + wr) {
            #pragma unroll
            for (int n = 0; n < 8; n++) {
                const int c = k0 + n * 8 + 2 * th;
                if (c     > rA) s[n][0] = -1e30f;
                if (c + 1 > rA) s[n][1] = -1e30f;
                if (c     > rB) s[n][2] = -1e30f;
                if (c + 1 > rB) s[n][3] = -1e30f;
            }
        }

        // ---- online softmax (rows g and g+8; quad holds all 64 cols) ----
        float rmA = -1e30f, rmB = -1e30f;
        #pragma unroll
        for (int n = 0; n < 8; n++) {
            rmA = fmaxf(rmA, fmaxf(s[n][0], s[n][1]));
            rmB = fmaxf(rmB, fmaxf(s[n][2], s[n][3]));
        }
        rmA = fmaxf(rmA, __shfl_xor_sync(0xffffffffu, rmA, 1));
        rmA = fmaxf(rmA, __shfl_xor_sync(0xffffffffu, rmA, 2));
        rmB = fmaxf(rmB, __shfl_xor_sync(0xffffffffu, rmB, 1));
        rmB = fmaxf(rmB, __shfl_xor_sync(0xffffffffu, rmB, 2));

        const float mnA = fmaxf(mA, rmA);
        const float mnB = fmaxf(mB, rmB);
        const float aA  = __expf(mA - mnA);
        const float aB  = __expf(mB - mnB);
        mA = mnA; mB = mnB;

        float sumA = 0.0f, sumB = 0.0f;
        #pragma unroll
        for (int n = 0; n < 8; n++) {
            s[n][0] = __expf(s[n][0] - mnA); sumA += s[n][0];
            s[n][1] = __expf(s[n][1] - mnA); sumA += s[n][1];
            s[n][2] = __expf(s[n][2] - mnB); sumB += s[n][2];
            s[n][3] = __expf(s[n][3] - mnB); sumB += s[n][3];
        }
        sumA += __shfl_xor_sync(0xffffffffu, sumA, 1);
        sumA += __shfl_xor_sync(0xffffffffu, sumA, 2);
        sumB += __shfl_xor_sync(0xffffffffu, sumB, 1);
        sumB += __shfl_xor_sync(0xffffffffu, sumB, 2);
        lA = lA * aA + sumA;
        lB = lB * aB + sumB;

        #pragma unroll
        for (int n = 0; n < 8; n++) {
            acc[n][0] *= aA; acc[n][1] *= aA;
            acc[n][2] *= aB; acc[n][3] *= aB;
        }

        // ---- P -> smem (tf32 bits); rows are warp-private ----
        #pragma unroll
        for (int n = 0; n < 8; n++) {
            uint2 pA = make_uint2(f2tf32(s[n][0]), f2tf32(s[n][1]));
            uint2 pB = make_uint2(f2tf32(s[n][2]), f2tf32(s[n][3]));
            *(uint2*)&sp[(wr + g    ) * PPITCH + n * 8 + 2 * th] = pA;
            *(uint2*)&sp[(wr + g + 8) * PPITCH + n * 8 + 2 * th] = pB;
        }
        __syncwarp();

        // ---- O += P V  (plain tf32) ----
        #pragma unroll
        for (int k = 0; k < 8; k++) {
            uint32_t pa[4];
            const float* p0 = &sp[(wr + g    ) * PPITCH + k * 8 + th];
            const float* p8 = &sp[(wr + g + 8) * PPITCH + k * 8 + th];
            pa[0] = __float_as_uint(p0[0]);
            pa[1] = __float_as_uint(p8[0]);
            pa[2] = __float_as_uint(p0[4]);
            pa[3] = __float_as_uint(p8[4]);
            #pragma unroll
            for (int n = 0; n < 8; n++) {
                const float* vp = &sv[(k * 8 + th) * VPITCH + n * 8 + g];
                uint32_t vb[2] = { __float_as_uint(vp[0]),
                                   __float_as_uint(vp[4 * VPITCH]) };
                mma_tf32(acc[n], pa, vb);
            }
        }
    }

    // ---- finalize -> ctx token-major [B,S,1024] ----
    const float iA = 1.0f / lA;
    const float iB = 1.0f / lB;
    const int b = bh >> 4;
    const int h = bh & 15;
    const size_t rowA = (size_t)b * SEQ + q0 + wr + g;
    const size_t rowB = rowA + 8;
    #pragma unroll
    for (int n = 0; n < 8; n++) {
        const int d = h * DEPTH + n * 8 + 2 * th;
        float2 oA = make_float2(acc[n][0] * iA, acc[n][1] * iA);
        float2 oB = make_float2(acc[n][2] * iB, acc[n][3] * iB);
        *(float2*)(ctx + rowA * DMODEL + d) = oA;
        *(float2*)(ctx + rowB * DMODEL + d) = oB;
    }
}

// ---------------------------------------------------------------------------
// Launch
// ---------------------------------------------------------------------------
extern "C" void kernel_launch(void* const* d_in, const int* in_sizes, int n_in,
                              void* d_out, int out_size)
{
    const float* q       = (const float*)d_in[0];
    const float* k       = (const float*)d_in[1];
    const float* v       = (const float*)d_in[2];
    const float* wq_w    = (const float*)d_in[3];
    const float* wq_b    = (const float*)d_in[4];
    const float* wk_w    = (const float*)d_in[5];
    const float* wk_b    = (const float*)d_in[6];
    const float* wv_w    = (const float*)d_in[7];
    const float* wv_b    = (const float*)d_in[8];
    const float* dense_w = (const float*)d_in[9];
    const float* dense_b = (const float*)d_in[10];
    float* out           = (float*)d_out;

    float *qh, *kh, *vh, *ctx;
    cudaGetSymbolAddress((void**)&qh,  g_qh);
    cudaGetSymbolAddress((void**)&kh,  g_kh);
    cudaGetSymbolAddress((void**)&vh,  g_vh);
    cudaGetSymbolAddress((void**)&ctx, g_ctx);

    const dim3 ggrid(DMODEL / 128, NTOK / 128);   // (8, 64)
    const dim3 gblk(256);

    // Projections -> head-major; fold softmax scale into Q.
    gemm_tf32_kernel<1><<<ggrid, gblk>>>(q, wq_w, wq_b, qh, NTOK, DMODEL, DMODEL, QK_SCALE);
    gemm_tf32_kernel<1><<<ggrid, gblk>>>(k, wk_w, wk_b, kh, NTOK, DMODEL, DMODEL, 1.0f);
    gemm_tf32_kernel<1><<<ggrid, gblk>>>(v, wv_w, wv_b, vh, NTOK, DMODEL, DMODEL, 1.0f);

    // Tensor-core flash attention (pipelined, 2-MMA QK)
    const int att_smem_bytes = ATT_SMEM_FLOATS * (int)sizeof(float);  // 106496
    cudaFuncSetAttribute(attn_mma_kernel, cudaFuncAttributeMaxDynamicSharedMemorySize,
                         att_smem_bytes);
    dim3 agrid(BATCH * NHEAD, SEQ / 128);         // (64, 16), bh fastest
    attn_mma_kernel<<<agrid, 256, att_smem_bytes>>>(qh, kh, vh, ctx);

    // Output dense
    gemm_tf32_kernel<0><<<ggrid, gblk>>>(ctx, dense_w, dense_b, out, NTOK, DMODEL, DMODEL, 1.0f);
}

// round 12
// speedup vs baseline: 4.0681x; 1.0088x over previous
#include <cuda_runtime.h>
#include <cuda_bf16.h>
#include <cstdint>

// Problem constants
#define BATCH     4
#define SEQ       2048
#define DMODEL    1024
#define NHEAD     16
#define DEPTH     64
#define NTOK      (BATCH * SEQ)          // 8192
// 1/sqrt(64) * log2(e): QK scale with exp2 conversion folded in
#define QK_SCALE_LOG2E 0.1803368801111183f

// ---------------------------------------------------------------------------
// Scratch buffers (allocations are forbidden; __device__ globals are allowed)
// ---------------------------------------------------------------------------
__device__ float g_qh [NTOK * DMODEL];   // [B,H,S,64] head-major, pre-scaled
__device__ float g_kh [NTOK * DMODEL];   // [B,H,S,64]
__device__ float g_vh [NTOK * DMODEL];   // [B,H,S,64]
__device__ float g_ctx[NTOK * DMODEL];   // [B,S,1024] token-major

// ---------------------------------------------------------------------------
// TF32 helpers
// ---------------------------------------------------------------------------
__device__ __forceinline__ uint32_t f2tf32(float x) {
    uint32_t r;
    asm("cvt.rna.tf32.f32 %0, %1;" : "=r"(r) : "f"(x));
    return r;
}

__device__ __forceinline__ void mma_tf32(float d[4],
                                         const uint32_t a[4],
                                         const uint32_t b[2]) {
    asm volatile(
        "mma.sync.aligned.m16n8k8.row.col.f32.tf32.tf32.f32 "
        "{%0,%1,%2,%3}, {%4,%5,%6,%7}, {%8,%9}, {%0,%1,%2,%3};\n"
        : "+f"(d[0]), "+f"(d[1]), "+f"(d[2]), "+f"(d[3])
        : "r"(a[0]), "r"(a[1]), "r"(a[2]), "r"(a[3]),
          "r"(b[0]), "r"(b[1]));
}

// ---------------------------------------------------------------------------
// TF32 GEMM: C = (A[M,K] @ W[N,K]^T + bias) * scale   (proven, unchanged)
// ---------------------------------------------------------------------------
#define GPAD 36

template <int MODE>
__global__ void __launch_bounds__(256, 2)
gemm_tf32_kernel(const float* __restrict__ A,
                 const float* __restrict__ W,
                 const float* __restrict__ bias,
                 float* __restrict__ C,
                 int M, int N, int K, float scale)
{
    __shared__ float As[128][GPAD];
    __shared__ float Bs[128][GPAD];

    const int tid  = threadIdx.x;
    const int warp = tid >> 5;
    const int lane = tid & 31;
    const int wm   = (warp >> 2) * 64;
    const int wn   = (warp & 3) * 32;
    const int g    = lane >> 2;
    const int th   = lane & 3;
    const int m0   = blockIdx.y * 128;
    const int n0   = blockIdx.x * 128;

    float acc[4][4][4];
    #pragma unroll
    for (int mi = 0; mi < 4; mi++)
        #pragma unroll
        for (int ni = 0; ni < 4; ni++)
            #pragma unroll
            for (int r = 0; r < 4; r++) acc[mi][ni][r] = 0.0f;

    const int grow = tid >> 3;
    const int gq   = tid & 7;
    const float* Abase = A + (size_t)(m0 + grow) * K + gq * 4;
    const float* Wbase = W + (size_t)(n0 + grow) * K + gq * 4;

    float4 ra[4], rb[4];
    #pragma unroll
    for (int i = 0; i < 4; i++) {
        ra[i] = *(const float4*)(Abase + (size_t)(i * 32) * K);
        rb[i] = *(const float4*)(Wbase + (size_t)(i * 32) * K);
    }

    for (int k0 = 0; k0 < K; k0 += 32) {
        #pragma unroll
        for (int i = 0; i < 4; i++) {
            uint4 ua = make_uint4(f2tf32(ra[i].x), f2tf32(ra[i].y),
                                  f2tf32(ra[i].z), f2tf32(ra[i].w));
            uint4 ub = make_uint4(f2tf32(rb[i].x), f2tf32(rb[i].y),
                                  f2tf32(rb[i].z), f2tf32(rb[i].w));
            *(uint4*)&As[grow + i * 32][gq * 4] = ua;
            *(uint4*)&Bs[grow + i * 32][gq * 4] = ub;
        }
        __syncthreads();

        if (k0 + 32 < K) {
            #pragma unroll
            for (int i = 0; i < 4; i++) {
                ra[i] = *(const float4*)(Abase + (size_t)(i * 32) * K + k0 + 32);
                rb[i] = *(const float4*)(Wbase + (size_t)(i * 32) * K + k0 + 32);
            }
        }

        #pragma unroll
        for (int k8 = 0; k8 < 4; k8++) {
            uint32_t af[4][4], bf[4][2];
            #pragma unroll
            for (int mi = 0; mi < 4; mi++) {
                const float* p = &As[wm + mi * 16 + g][k8 * 8 + th];
                af[mi][0] = __float_as_uint(p[0]);
                af[mi][1] = __float_as_uint(p[8 * GPAD]);
                af[mi][2] = __float_as_uint(p[4]);
                af[mi][3] = __float_as_uint(p[8 * GPAD + 4]);
            }
            #pragma unroll
            for (int ni = 0; ni < 4; ni++) {
                const float* p = &Bs[wn + ni * 8 + g][k8 * 8 + th];
                bf[ni][0] = __float_as_uint(p[0]);
                bf[ni][1] = __float_as_uint(p[4]);
            }
            #pragma unroll
            for (int mi = 0; mi < 4; mi++)
                #pragma unroll
                for (int ni = 0; ni < 4; ni++)
                    mma_tf32(acc[mi][ni], af[mi], bf[ni]);
        }
        __syncthreads();
    }

    #pragma unroll
    for (int mi = 0; mi < 4; mi++) {
        #pragma unroll
        for (int ni = 0; ni < 4; ni++) {
            const int n  = n0 + wn + ni * 8 + th * 2;
            const float2 bv = *(const float2*)(bias + n);
            const int mA = m0 + wm + mi * 16 + g;
            const int mB = mA + 8;
            float2 vA, vB;
            vA.x = (acc[mi][ni][0] + bv.x) * scale;
            vA.y = (acc[mi][ni][1] + bv.y) * scale;
            vB.x = (acc[mi][ni][2] + bv.x) * scale;
            vB.y = (acc[mi][ni][3] + bv.y) * scale;
            if (MODE == 0) {
                *(float2*)(C + (size_t)mA * N + n) = vA;
                *(float2*)(C + (size_t)mB * N + n) = vB;
            } else {
                const int h = n >> 6;
                const int d = n & (DEPTH - 1);
                {
                    const int b = mA >> 11, s = mA & (SEQ - 1);
                    *(float2*)(C + (((size_t)(b * NHEAD + h)) * SEQ + s) * DEPTH + d) = vA;
                }
                {
                    const int b = mB >> 11, s = mB & (SEQ - 1);
                    *(float2*)(C + (((size_t)(b * NHEAD + h)) * SEQ + s) * DEPTH + d) = vB;
                }
            }
        }
    }
}

// ---------------------------------------------------------------------------
// Tensor-core flash attention (causal), 2 CTAs/SM for phase overlap.
//   Br=64 queries per CTA (4 warps x 16 rows), Bc=64 keys per tile.
//   S = Q K^T via 2 MMAs (qh*kh + ql*kh). O += P V via plain tf32.
//   Logits carry log2(e) folded into the Q projection -> exp2f softmax.
//   Two co-resident CTAs desynchronize: one CTA's MMAs cover the other's
//   load/softmax phases.
// ---------------------------------------------------------------------------
#define KPITCH 68   // 68 % 32 == 4  -> b-frag LDS bank = lane (conflict-free)
#define VPITCH 72   // 72 % 32 == 8  -> b-frag LDS bank = 8*th+g (conflict-free)
#define PPITCH 68

#define ATT_SMEM_FLOATS (64 * KPITCH + 64 * VPITCH + 64 * PPITCH)  // 13312 fl

extern __shared__ float att_smem[];

__global__ void __launch_bounds__(128, 2)
attn_mma_kernel(const float* __restrict__ Q,
                const float* __restrict__ K,
                const float* __restrict__ V,
                float* __restrict__ ctx)
{
    float* skh = att_smem;                    // [64][KPITCH] K (tf32 bits)
    float* sv  = skh + 64 * KPITCH;           // [64][VPITCH] V (tf32 bits)
    float* sp  = sv  + 64 * VPITCH;           // [64][PPITCH] P (tf32 bits)

    const int tid  = threadIdx.x;
    const int warp = tid >> 5;
    const int lane = tid & 31;
    const int g    = lane >> 2;
    const int th   = lane & 3;

    const int bh   = blockIdx.x;              // head-major: balanced waves
    const int qidx = blockIdx.y;
    const int q0   = qidx * 64;
    const int wr   = warp * 16;               // CTA-local row base of this warp

    const float* Qb = Q + ((size_t)bh * SEQ + q0 + wr) * DEPTH;
    const float* Kb = K + (size_t)bh * SEQ * DEPTH;
    const float* Vb = V + (size_t)bh * SEQ * DEPTH;

    // per-thread gmem load mapping (row, col4) for 64x64 tiles, 128 threads
    const int lrow = tid >> 4;                // 0..7, +8 per i
    const int lc4  = tid & 15;

    // ---- Q fragments, hi+lo, loaded once (rows g, g+8 of warp block) ----
    uint32_t qhi[8][4], qlo[8][4];
    #pragma unroll
    for (int j = 0; j < 8; j++) {
        float x[4];
        x[0] = Qb[(size_t)g       * DEPTH + j * 8 + th];
        x[1] = Qb[(size_t)(g + 8) * DEPTH + j * 8 + th];
        x[2] = Qb[(size_t)g       * DEPTH + j * 8 + th + 4];
        x[3] = Qb[(size_t)(g + 8) * DEPTH + j * 8 + th + 4];
        #pragma unroll
        for (int r = 0; r < 4; r++) {
            uint32_t h = f2tf32(x[r]);
            qhi[j][r] = h;
            qlo[j][r] = f2tf32(x[r] - __uint_as_float(h));
        }
    }

    float acc[8][4];
    #pragma unroll
    for (int n = 0; n < 8; n++)
        #pragma unroll
        for (int r = 0; r < 4; r++) acc[n][r] = 0.0f;

    float mA = -1e30f, mB = -1e30f, lA = 0.0f, lB = 0.0f;

    const int nkt = qidx + 1;

    for (int kt = 0; kt < nkt; kt++) {
        const int k0 = kt * 64;
        __syncthreads();   // previous compute done reading skh/sv
        // ---- cooperative K/V tile load + tf32 conversion (128 threads) ----
        #pragma unroll
        for (int i = 0; i < 8; i++) {
            const int row = lrow + i * 8;
            float4 kxv = *(const float4*)(Kb + (size_t)(k0 + row) * DEPTH + lc4 * 4);
            float4 vxv = *(const float4*)(Vb + (size_t)(k0 + row) * DEPTH + lc4 * 4);
            uint4 h = make_uint4(f2tf32(kxv.x), f2tf32(kxv.y),
                                 f2tf32(kxv.z), f2tf32(kxv.w));
            *(uint4*)&skh[row * KPITCH + lc4 * 4] = h;
            uint4 vq = make_uint4(f2tf32(vxv.x), f2tf32(vxv.y),
                                  f2tf32(vxv.z), f2tf32(vxv.w));
            *(uint4*)&sv[row * VPITCH + lc4 * 4] = vq;
        }
        __syncthreads();

        // ---- S = Q K^T  (2 MMAs: qh*kh + ql*kh) ----
        float s[8][4];
        #pragma unroll
        for (int n = 0; n < 8; n++)
            #pragma unroll
            for (int r = 0; r < 4; r++) s[n][r] = 0.0f;

        #pragma unroll
        for (int k = 0; k < 8; k++) {
            #pragma unroll
            for (int n = 0; n < 8; n++) {
                const float* hp = &skh[(n * 8 + g) * KPITCH + k * 8 + th];
                uint32_t bhf[2] = { __float_as_uint(hp[0]), __float_as_uint(hp[4]) };
                mma_tf32(s[n], qhi[k], bhf);
                mma_tf32(s[n], qlo[k], bhf);
            }
        }

        // ---- causal mask (only tiles that can touch the diagonal) ----
        const int rA = q0 + wr + g;
        const int rB = rA + 8;
        if (k0 + 63 > q0 + wr) {
            #pragma unroll
            for (int n = 0; n < 8; n++) {
                const int c = k0 + n * 8 + 2 * th;
                if (c     > rA) s[n][0] = -1e30f;
                if (c + 1 > rA) s[n][1] = -1e30f;
                if (c     > rB) s[n][2] = -1e30f;
                if (c + 1 > rB) s[n][3] = -1e30f;
            }
        }

        // ---- online softmax in log2 domain (rows g and g+8) ----
        float rmA = -1e30f, rmB = -1e30f;
        #pragma unroll
        for (int n = 0; n < 8; n++) {
            rmA = fmaxf(rmA, fmaxf(s[n][0], s[n][1]));
            rmB = fmaxf(rmB, fmaxf(s[n][2], s[n][3]));
        }
        rmA = fmaxf(rmA, __shfl_xor_sync(0xffffffffu, rmA, 1));
        rmA = fmaxf(rmA, __shfl_xor_sync(0xffffffffu, rmA, 2));
        rmB = fmaxf(rmB, __shfl_xor_sync(0xffffffffu, rmB, 1));
        rmB = fmaxf(rmB, __shfl_xor_sync(0xffffffffu, rmB, 2));

        const float mnA = fmaxf(mA, rmA);
        const float mnB = fmaxf(mB, rmB);
        const float aA  = exp2f(mA - mnA);
        const float aB  = exp2f(mB - mnB);
        mA = mnA; mB = mnB;

        float sumA = 0.0f, sumB = 0.0f;
        #pragma unroll
        for (int n = 0; n < 8; n++) {
            s[n][0] = exp2f(s[n][0] - mnA); sumA += s[n][0];
            s[n][1] = exp2f(s[n][1] - mnA); sumA += s[n][1];
            s[n][2] = exp2f(s[n][2] - mnB); sumB += s[n][2];
            s[n][3] = exp2f(s[n][3] - mnB); sumB += s[n][3];
        }
        sumA += __shfl_xor_sync(0xffffffffu, sumA, 1);
        sumA += __shfl_xor_sync(0xffffffffu, sumA, 2);
        sumB += __shfl_xor_sync(0xffffffffu, sumB, 1);
        sumB += __shfl_xor_sync(0xffffffffu, sumB, 2);
        lA = lA * aA + sumA;
        lB = lB * aB + sumB;

        #pragma unroll
        for (int n = 0; n < 8; n++) {
            acc[n][0] *= aA; acc[n][1] *= aA;
            acc[n][2] *= aB; acc[n][3] *= aB;
        }

        // ---- P -> smem (tf32 bits); rows are warp-private ----
        #pragma unroll
        for (int n = 0; n < 8; n++) {
            uint2 pA = make_uint2(f2tf32(s[n][0]), f2tf32(s[n][1]));
            uint2 pB = make_uint2(f2tf32(s[n][2]), f2tf32(s[n][3]));
            *(uint2*)&sp[(wr + g    ) * PPITCH + n * 8 + 2 * th] = pA;
            *(uint2*)&sp[(wr + g + 8) * PPITCH + n * 8 + 2 * th] = pB;
        }
        __syncwarp();

        // ---- O += P V  (plain tf32) ----
        #pragma unroll
        for (int k = 0; k < 8; k++) {
            uint32_t pa[4];
            const float* p0 = &sp[(wr + g    ) * PPITCH + k * 8 + th];
            const float* p8 = &sp[(wr + g + 8) * PPITCH + k * 8 + th];
            pa[0] = __float_as_uint(p0[0]);
            pa[1] = __float_as_uint(p8[0]);
            pa[2] = __float_as_uint(p0[4]);
            pa[3] = __float_as_uint(p8[4]);
            #pragma unroll
            for (int n = 0; n < 8; n++) {
                const float* vp = &sv[(k * 8 + th) * VPITCH + n * 8 + g];
                uint32_t vb[2] = { __float_as_uint(vp[0]),
                                   __float_as_uint(vp[4 * VPITCH]) };
                mma_tf32(acc[n], pa, vb);
            }
        }
    }

    // ---- finalize -> ctx token-major [B,S,1024] ----
    const float iA = 1.0f / lA;
    const float iB = 1.0f / lB;
    const int b = bh >> 4;
    const int h = bh & 15;
    const size_t rowA = (size_t)b * SEQ + q0 + wr + g;
    const size_t rowB = rowA + 8;
    #pragma unroll
    for (int n = 0; n < 8; n++) {
        const int d = h * DEPTH + n * 8 + 2 * th;
        float2 oA = make_float2(acc[n][0] * iA, acc[n][1] * iA);
        float2 oB = make_float2(acc[n][2] * iB, acc[n][3] * iB);
        *(float2*)(ctx + rowA * DMODEL + d) = oA;
        *(float2*)(ctx + rowB * DMODEL + d) = oB;
    }
}

// ---------------------------------------------------------------------------
// Launch
// ---------------------------------------------------------------------------
extern "C" void kernel_launch(void* const* d_in, const int* in_sizes, int n_in,
                              void* d_out, int out_size)
{
    const float* q       = (const float*)d_in[0];
    const float* k       = (const float*)d_in[1];
    const float* v       = (const float*)d_in[2];
    const float* wq_w    = (const float*)d_in[3];
    const float* wq_b    = (const float*)d_in[4];
    const float* wk_w    = (const float*)d_in[5];
    const float* wk_b    = (const float*)d_in[6];
    const float* wv_w    = (const float*)d_in[7];
    const float* wv_b    = (const float*)d_in[8];
    const float* dense_w = (const float*)d_in[9];
    const float* dense_b = (const float*)d_in[10];
    float* out           = (float*)d_out;

    float *qh, *kh, *vh, *ctx;
    cudaGetSymbolAddress((void**)&qh,  g_qh);
    cudaGetSymbolAddress((void**)&kh,  g_kh);
    cudaGetSymbolAddress((void**)&vh,  g_vh);
    cudaGetSymbolAddress((void**)&ctx, g_ctx);

    const dim3 ggrid(DMODEL / 128, NTOK / 128);   // (8, 64)
    const dim3 gblk(256);

    // Projections -> head-major; fold softmax scale * log2(e) into Q.
    gemm_tf32_kernel<1><<<ggrid, gblk>>>(q, wq_w, wq_b, qh, NTOK, DMODEL, DMODEL, QK_SCALE_LOG2E);
    gemm_tf32_kernel<1><<<ggrid, gblk>>>(k, wk_w, wk_b, kh, NTOK, DMODEL, DMODEL, 1.0f);
    gemm_tf32_kernel<1><<<ggrid, gblk>>>(v, wv_w, wv_b, vh, NTOK, DMODEL, DMODEL, 1.0f);

    // Tensor-core flash attention (Br=64, 2 CTAs/SM)
    const int att_smem_bytes = ATT_SMEM_FLOATS * (int)sizeof(float);  // 53248
    cudaFuncSetAttribute(attn_mma_kernel, cudaFuncAttributeMaxDynamicSharedMemorySize,
                         att_smem_bytes);
    dim3 agrid(BATCH * NHEAD, SEQ / 64);          // (64, 32), bh fastest
    attn_mma_kernel<<<agrid, 128, att_smem_bytes>>>(qh, kh, vh, ctx);

    // Output dense
    gemm_tf32_kernel<0><<<ggrid, gblk>>>(ctx, dense_w, dense_b, out, NTOK, DMODEL, DMODEL, 1.0f);
}

// round 14
// speedup vs baseline: 4.5839x; 1.1268x over previous
#include <cuda_runtime.h>
#include <cuda_bf16.h>
#include <cuda_fp16.h>
#include <cstdint>

// Problem constants
#define BATCH     4
#define SEQ       2048
#define DMODEL    1024
#define NHEAD     16
#define DEPTH     64
#define NTOK      (BATCH * SEQ)          // 8192
// 1/sqrt(64) * log2(e): QK scale with exp2 conversion folded in
#define QK_SCALE_LOG2E 0.1803368801111183f

// ---------------------------------------------------------------------------
// Scratch buffers
// ---------------------------------------------------------------------------
__device__ float g_qh [NTOK * DMODEL];   // [B,H,S,64] head-major, pre-scaled
__device__ float g_kh [NTOK * DMODEL];   // [B,H,S,64]
__device__ float g_vh [NTOK * DMODEL];   // [B,H,S,64]
__device__ float g_ctx[NTOK * DMODEL];   // [B,S,1024] token-major

// ---------------------------------------------------------------------------
// Helpers
// ---------------------------------------------------------------------------
__device__ __forceinline__ uint32_t f2tf32(float x) {
    uint32_t r;
    asm("cvt.rna.tf32.f32 %0, %1;" : "=r"(r) : "f"(x));
    return r;
}

__device__ __forceinline__ void mma_tf32(float d[4],
                                         const uint32_t a[4],
                                         const uint32_t b[2]) {
    asm volatile(
        "mma.sync.aligned.m16n8k8.row.col.f32.tf32.tf32.f32 "
        "{%0,%1,%2,%3}, {%4,%5,%6,%7}, {%8,%9}, {%0,%1,%2,%3};\n"
        : "+f"(d[0]), "+f"(d[1]), "+f"(d[2]), "+f"(d[3])
        : "r"(a[0]), "r"(a[1]), "r"(a[2]), "r"(a[3]),
          "r"(b[0]), "r"(b[1]));
}

__device__ __forceinline__ void mma_f16(float d[4],
                                        const uint32_t a[4],
                                        const uint32_t b[2]) {
    asm volatile(
        "mma.sync.aligned.m16n8k16.row.col.f32.f16.f16.f32 "
        "{%0,%1,%2,%3}, {%4,%5,%6,%7}, {%8,%9}, {%0,%1,%2,%3};\n"
        : "+f"(d[0]), "+f"(d[1]), "+f"(d[2]), "+f"(d[3])
        : "r"(a[0]), "r"(a[1]), "r"(a[2]), "r"(a[3]),
          "r"(b[0]), "r"(b[1]));
}

__device__ __forceinline__ uint32_t h2_to_u32(__half2 h) {
    return *reinterpret_cast<uint32_t*>(&h);
}

// ---------------------------------------------------------------------------
// FP16 GEMM: C = (A[M,K] @ W[N,K]^T + bias) * scale
// 128x128 tile, BK=32, 256 threads (8 warps as 2x4), warp tile 64x32.
// fp16 m16n8k16 MMAs, fp32 accumulation. Inputs converted with rn rounding
// (2^-11 relative error — same class as tf32-rna).
// MODE 0: C[m*N + n]   MODE 1: head-major scatter.
// Smem pitch 36 halves (72B): fragment LDS bank = (18*row + th) mod 32,
// 18g mod 32 = {0,18,4,22,8,26,12,30} -> all 32 lanes distinct.
// ---------------------------------------------------------------------------
#define HPAD 36

template <int MODE>
__global__ void __launch_bounds__(256, 2)
gemm_f16_kernel(const float* __restrict__ A,
                const float* __restrict__ W,
                const float* __restrict__ bias,
                float* __restrict__ C,
                int M, int N, int K, float scale)
{
    __shared__ __half As[128][HPAD];
    __shared__ __half Bs[128][HPAD];

    const int tid  = threadIdx.x;
    const int warp = tid >> 5;
    const int lane = tid & 31;
    const int wm   = (warp >> 2) * 64;
    const int wn   = (warp & 3) * 32;
    const int g    = lane >> 2;
    const int th   = lane & 3;
    const int m0   = blockIdx.y * 128;
    const int n0   = blockIdx.x * 128;

    float acc[4][4][4];
    #pragma unroll
    for (int mi = 0; mi < 4; mi++)
        #pragma unroll
        for (int ni = 0; ni < 4; ni++)
            #pragma unroll
            for (int r = 0; r < 4; r++) acc[mi][ni][r] = 0.0f;

    const int grow = tid >> 3;            // 0..31, +32 per i
    const int gq   = tid & 7;             // float4 index within 32-wide k
    const float* Abase = A + (size_t)(m0 + grow) * K + gq * 4;
    const float* Wbase = W + (size_t)(n0 + grow) * K + gq * 4;

    float4 ra[4], rb[4];
    #pragma unroll
    for (int i = 0; i < 4; i++) {
        ra[i] = *(const float4*)(Abase + (size_t)(i * 32) * K);
        rb[i] = *(const float4*)(Wbase + (size_t)(i * 32) * K);
    }

    for (int k0 = 0; k0 < K; k0 += 32) {
        // Store tiles to smem as fp16 (rn). 8B per thread per row-chunk.
        #pragma unroll
        for (int i = 0; i < 4; i++) {
            const int row = grow + i * 32;
            uint2 ua = make_uint2(
                h2_to_u32(__floats2half2_rn(ra[i].x, ra[i].y)),
                h2_to_u32(__floats2half2_rn(ra[i].z, ra[i].w)));
            uint2 ub = make_uint2(
                h2_to_u32(__floats2half2_rn(rb[i].x, rb[i].y)),
                h2_to_u32(__floats2half2_rn(rb[i].z, rb[i].w)));
            *(uint2*)&As[row][gq * 4] = ua;
            *(uint2*)&Bs[row][gq * 4] = ub;
        }
        __syncthreads();

        // Prefetch next k-chunk while MMAs run.
        if (k0 + 32 < K) {
            #pragma unroll
            for (int i = 0; i < 4; i++) {
                ra[i] = *(const float4*)(Abase + (size_t)(i * 32) * K + k0 + 32);
                rb[i] = *(const float4*)(Wbase + (size_t)(i * 32) * K + k0 + 32);
            }
        }

        #pragma unroll
        for (int ks = 0; ks < 2; ks++) {      // two k16 steps per chunk
            const int kb = ks * 16;
            uint32_t af[4][4], bf[4][2];
            #pragma unroll
            for (int mi = 0; mi < 4; mi++) {
                const int row = wm + mi * 16 + g;
                af[mi][0] = *(const uint32_t*)&As[row    ][kb + 2 * th];
                af[mi][1] = *(const uint32_t*)&As[row + 8][kb + 2 * th];
                af[mi][2] = *(const uint32_t*)&As[row    ][kb + 8 + 2 * th];
                af[mi][3] = *(const uint32_t*)&As[row + 8][kb + 8 + 2 * th];
            }
            #pragma unroll
            for (int ni = 0; ni < 4; ni++) {
                const int row = wn + ni * 8 + g;
                bf[ni][0] = *(const uint32_t*)&Bs[row][kb + 2 * th];
                bf[ni][1] = *(const uint32_t*)&Bs[row][kb + 8 + 2 * th];
            }
            #pragma unroll
            for (int mi = 0; mi < 4; mi++)
                #pragma unroll
                for (int ni = 0; ni < 4; ni++)
                    mma_f16(acc[mi][ni], af[mi], bf[ni]);
        }
        __syncthreads();
    }

    // Epilogue: d0=(g,2th) d1=(g,2th+1) d2=(g+8,2th) d3=(g+8,2th+1)
    #pragma unroll
    for (int mi = 0; mi < 4; mi++) {
        #pragma unroll
        for (int ni = 0; ni < 4; ni++) {
            const int n  = n0 + wn + ni * 8 + th * 2;
            const float2 bv = *(const float2*)(bias + n);
            const int mA = m0 + wm + mi * 16 + g;
            const int mB = mA + 8;
            float2 vA, vB;
            vA.x = (acc[mi][ni][0] + bv.x) * scale;
            vA.y = (acc[mi][ni][1] + bv.y) * scale;
            vB.x = (acc[mi][ni][2] + bv.x) * scale;
            vB.y = (acc[mi][ni][3] + bv.y) * scale;
            if (MODE == 0) {
                *(float2*)(C + (size_t)mA * N + n) = vA;
                *(float2*)(C + (size_t)mB * N + n) = vB;
            } else {
                const int h = n >> 6;
                const int d = n & (DEPTH - 1);
                {
                    const int b = mA >> 11, s = mA & (SEQ - 1);
                    *(float2*)(C + (((size_t)(b * NHEAD + h)) * SEQ + s) * DEPTH + d) = vA;
                }
                {
                    const int b = mB >> 11, s = mB & (SEQ - 1);
                    *(float2*)(C + (((size_t)(b * NHEAD + h)) * SEQ + s) * DEPTH + d) = vB;
                }
            }
        }
    }
}

// ---------------------------------------------------------------------------
// Tensor-core flash attention (unchanged from round 12 best).
//   Br=64 queries per CTA (4 warps x 16 rows), Bc=64 keys per tile.
//   S = Q K^T via 2 tf32 MMAs (qh*kh + ql*kh). O += P V via plain tf32.
//   exp2-domain softmax (log2(e) folded into Q projection scale).
// ---------------------------------------------------------------------------
#define KPITCH 68
#define VPITCH 72
#define PPITCH 68

#define ATT_SMEM_FLOATS (64 * KPITCH + 64 * VPITCH + 64 * PPITCH)  // 13312 fl

extern __shared__ float att_smem[];

__global__ void __launch_bounds__(128, 2)
attn_mma_kernel(const float* __restrict__ Q,
                const float* __restrict__ K,
                const float* __restrict__ V,
                float* __restrict__ ctx)
{
    float* skh = att_smem;                    // [64][KPITCH] K (tf32 bits)
    float* sv  = skh + 64 * KPITCH;           // [64][VPITCH] V (tf32 bits)
    float* sp  = sv  + 64 * VPITCH;           // [64][PPITCH] P (tf32 bits)

    const int tid  = threadIdx.x;
    const int warp = tid >> 5;
    const int lane = tid & 31;
    const int g    = lane >> 2;
    const int th   = lane & 3;

    const int bh   = blockIdx.x;
    const int qidx = blockIdx.y;
    const int q0   = qidx * 64;
    const int wr   = warp * 16;

    const float* Qb = Q + ((size_t)bh * SEQ + q0 + wr) * DEPTH;
    const float* Kb = K + (size_t)bh * SEQ * DEPTH;
    const float* Vb = V + (size_t)bh * SEQ * DEPTH;

    const int lrow = tid >> 4;
    const int lc4  = tid & 15;

    uint32_t qhi[8][4], qlo[8][4];
    #pragma unroll
    for (int j = 0; j < 8; j++) {
        float x[4];
        x[0] = Qb[(size_t)g       * DEPTH + j * 8 + th];
        x[1] = Qb[(size_t)(g + 8) * DEPTH + j * 8 + th];
        x[2] = Qb[(size_t)g       * DEPTH + j * 8 + th + 4];
        x[3] = Qb[(size_t)(g + 8) * DEPTH + j * 8 + th + 4];
        #pragma unroll
        for (int r = 0; r < 4; r++) {
            uint32_t h = f2tf32(x[r]);
            qhi[j][r] = h;
            qlo[j][r] = f2tf32(x[r] - __uint_as_float(h));
        }
    }

    float acc[8][4];
    #pragma unroll
    for (int n = 0; n < 8; n++)
        #pragma unroll
        for (int r = 0; r < 4; r++) acc[n][r] = 0.0f;

    float mA = -1e30f, mB = -1e30f, lA = 0.0f, lB = 0.0f;

    const int nkt = qidx + 1;

    for (int kt = 0; kt < nkt; kt++) {
        const int k0 = kt * 64;
        __syncthreads();
        #pragma unroll
        for (int i = 0; i < 8; i++) {
            const int row = lrow + i * 8;
            float4 kxv = *(const float4*)(Kb + (size_t)(k0 + row) * DEPTH + lc4 * 4);
            float4 vxv = *(const float4*)(Vb + (size_t)(k0 + row) * DEPTH + lc4 * 4);
            uint4 h = make_uint4(f2tf32(kxv.x), f2tf32(kxv.y),
                                 f2tf32(kxv.z), f2tf32(kxv.w));
            *(uint4*)&skh[row * KPITCH + lc4 * 4] = h;
            uint4 vq = make_uint4(f2tf32(vxv.x), f2tf32(vxv.y),
                                  f2tf32(vxv.z), f2tf32(vxv.w));
            *(uint4*)&sv[row * VPITCH + lc4 * 4] = vq;
        }
        __syncthreads();

        float s[8][4];
        #pragma unroll
        for (int n = 0; n < 8; n++)
            #pragma unroll
            for (int r = 0; r < 4; r++) s[n][r] = 0.0f;

        #pragma unroll
        for (int k = 0; k < 8; k++) {
            #pragma unroll
            for (int n = 0; n < 8; n++) {
                const float* hp = &skh[(n * 8 + g) * KPITCH + k * 8 + th];
                uint32_t bhf[2] = { __float_as_uint(hp[0]), __float_as_uint(hp[4]) };
                mma_tf32(s[n], qhi[k], bhf);
                mma_tf32(s[n], qlo[k], bhf);
            }
        }

        const int rA = q0 + wr + g;
        const int rB = rA + 8;
        if (k0 + 63 > q0 + wr) {
            #pragma unroll
            for (int n = 0; n < 8; n++) {
                const int c = k0 + n * 8 + 2 * th;
                if (c     > rA) s[n][0] = -1e30f;
                if (c + 1 > rA) s[n][1] = -1e30f;
                if (c     > rB) s[n][2] = -1e30f;
                if (c + 1 > rB) s[n][3] = -1e30f;
            }
        }

        float rmA = -1e30f, rmB = -1e30f;
        #pragma unroll
        for (int n = 0; n < 8; n++) {
            rmA = fmaxf(rmA, fmaxf(s[n][0], s[n][1]));
            rmB = fmaxf(rmB, fmaxf(s[n][2], s[n][3]));
        }
        rmA = fmaxf(rmA, __shfl_xor_sync(0xffffffffu, rmA, 1));
        rmA = fmaxf(rmA, __shfl_xor_sync(0xffffffffu, rmA, 2));
        rmB = fmaxf(rmB, __shfl_xor_sync(0xffffffffu, rmB, 1));
        rmB = fmaxf(rmB, __shfl_xor_sync(0xffffffffu, rmB, 2));

        const float mnA = fmaxf(mA, rmA);
        const float mnB = fmaxf(mB, rmB);
        const float aA  = exp2f(mA - mnA);
        const float aB  = exp2f(mB - mnB);
        mA = mnA; mB = mnB;

        float sumA = 0.0f, sumB = 0.0f;
        #pragma unroll
        for (int n = 0; n < 8; n++) {
            s[n][0] = exp2f(s[n][0] - mnA); sumA += s[n][0];
            s[n][1] = exp2f(s[n][1] - mnA); sumA += s[n][1];
            s[n][2] = exp2f(s[n][2] - mnB); sumB += s[n][2];
            s[n][3] = exp2f(s[n][3] - mnB); sumB += s[n][3];
        }
        sumA += __shfl_xor_sync(0xffffffffu, sumA, 1);
        sumA += __shfl_xor_sync(0xffffffffu, sumA, 2);
        sumB += __shfl_xor_sync(0xffffffffu, sumB, 1);
        sumB += __shfl_xor_sync(0xffffffffu, sumB, 2);
        lA = lA * aA + sumA;
        lB = lB * aB + sumB;

        #pragma unroll
        for (int n = 0; n < 8; n++) {
            acc[n][0] *= aA; acc[n][1] *= aA;
            acc[n][2] *= aB; acc[n][3] *= aB;
        }

        #pragma unroll
        for (int n = 0; n < 8; n++) {
            uint2 pA = make_uint2(f2tf32(s[n][0]), f2tf32(s[n][1]));
            uint2 pB = make_uint2(f2tf32(s[n][2]), f2tf32(s[n][3]));
            *(uint2*)&sp[(wr + g    ) * PPITCH + n * 8 + 2 * th] = pA;
            *(uint2*)&sp[(wr + g + 8) * PPITCH + n * 8 + 2 * th] = pB;
        }
        __syncwarp();

        #pragma unroll
        for (int k = 0; k < 8; k++) {
            uint32_t pa[4];
            const float* p0 = &sp[(wr + g    ) * PPITCH + k * 8 + th];
            const float* p8 = &sp[(wr + g + 8) * PPITCH + k * 8 + th];
            pa[0] = __float_as_uint(p0[0]);
            pa[1] = __float_as_uint(p8[0]);
            pa[2] = __float_as_uint(p0[4]);
            pa[3] = __float_as_uint(p8[4]);
            #pragma unroll
            for (int n = 0; n < 8; n++) {
                const float* vp = &sv[(k * 8 + th) * VPITCH + n * 8 + g];
                uint32_t vb[2] = { __float_as_uint(vp[0]),
                                   __float_as_uint(vp[4 * VPITCH]) };
                mma_tf32(acc[n], pa, vb);
            }
        }
    }

    const float iA = 1.0f / lA;
    const float iB = 1.0f / lB;
    const int b = bh >> 4;
    const int h = bh & 15;
    const size_t rowA = (size_t)b * SEQ + q0 + wr + g;
    const size_t rowB = rowA + 8;
    #pragma unroll
    for (int n = 0; n < 8; n++) {
        const int d = h * DEPTH + n * 8 + 2 * th;
        float2 oA = make_float2(acc[n][0] * iA, acc[n][1] * iA);
        float2 oB = make_float2(acc[n][2] * iB, acc[n][3] * iB);
        *(float2*)(ctx + rowA * DMODEL + d) = oA;
        *(float2*)(ctx + rowB * DMODEL + d) = oB;
    }
}

// ---------------------------------------------------------------------------
// Launch
// ---------------------------------------------------------------------------
extern "C" void kernel_launch(void* const* d_in, const int* in_sizes, int n_in,
                              void* d_out, int out_size)
{
    const float* q       = (const float*)d_in[0];
    const float* k       = (const float*)d_in[1];
    const float* v       = (const float*)d_in[2];
    const float* wq_w    = (const float*)d_in[3];
    const float* wq_b    = (const float*)d_in[4];
    const float* wk_w    = (const float*)d_in[5];
    const float* wk_b    = (const float*)d_in[6];
    const float* wv_w    = (const float*)d_in[7];
    const float* wv_b    = (const float*)d_in[8];
    const float* dense_w = (const float*)d_in[9];
    const float* dense_b = (const float*)d_in[10];
    float* out           = (float*)d_out;

    float *qh, *kh, *vh, *ctx;
    cudaGetSymbolAddress((void**)&qh,  g_qh);
    cudaGetSymbolAddress((void**)&kh,  g_kh);
    cudaGetSymbolAddress((void**)&vh,  g_vh);
    cudaGetSymbolAddress((void**)&ctx, g_ctx);

    const dim3 ggrid(DMODEL / 128, NTOK / 128);   // (8, 64)
    const dim3 gblk(256);

    // Projections -> head-major; fold softmax scale * log2(e) into Q.
    gemm_f16_kernel<1><<<ggrid, gblk>>>(q, wq_w, wq_b, qh, NTOK, DMODEL, DMODEL, QK_SCALE_LOG2E);
    gemm_f16_kernel<1><<<ggrid, gblk>>>(k, wk_w, wk_b, kh, NTOK, DMODEL, DMODEL, 1.0f);
    gemm_f16_kernel<1><<<ggrid, gblk>>>(v, wv_w, wv_b, vh, NTOK, DMODEL, DMODEL, 1.0f);

    // Tensor-core flash attention (Br=64, 2 CTAs/SM) — unchanged
    const int att_smem_bytes = ATT_SMEM_FLOATS * (int)sizeof(float);  // 53248
    cudaFuncSetAttribute(attn_mma_kernel, cudaFuncAttributeMaxDynamicSharedMemorySize,
                         att_smem_bytes);
    dim3 agrid(BATCH * NHEAD, SEQ / 64);          // (64, 32), bh fastest
    attn_mma_kernel<<<agrid, 128, att_smem_bytes>>>(qh, kh, vh, ctx);

    // Output dense
    gemm_f16_kernel<0><<<ggrid, gblk>>>(ctx, dense_w, dense_b, out, NTOK, DMODEL, DMODEL, 1.0f);
}

// round 17
// speedup vs baseline: 5.4198x; 1.1824x over previous
#include <cuda_runtime.h>
#include <cuda_bf16.h>
#include <cuda_fp16.h>
#include <cstdint>

// Problem constants
#define BATCH     4
#define SEQ       2048
#define DMODEL    1024
#define NHEAD     16
#define DEPTH     64
#define NTOK      (BATCH * SEQ)          // 8192
// 1/sqrt(64) * log2(e): QK scale with exp2 conversion folded in
#define QK_SCALE_LOG2E 0.1803368801111183f

// ---------------------------------------------------------------------------
// Scratch buffers
// ---------------------------------------------------------------------------
__device__ float g_qh [NTOK * DMODEL];   // [B,H,S,64] head-major, pre-scaled
__device__ float g_kh [NTOK * DMODEL];   // [B,H,S,64]
__device__ float g_vh [NTOK * DMODEL];   // [B,H,S,64]
__device__ float g_ctx[NTOK * DMODEL];   // [B,S,1024] token-major

// ---------------------------------------------------------------------------
// Helpers
// ---------------------------------------------------------------------------
__device__ __forceinline__ uint32_t f2tf32(float x) {
    uint32_t r;
    asm("cvt.rna.tf32.f32 %0, %1;" : "=r"(r) : "f"(x));
    return r;
}

__device__ __forceinline__ void mma_tf32(float d[4],
                                         const uint32_t a[4],
                                         const uint32_t b[2]) {
    asm volatile(
        "mma.sync.aligned.m16n8k8.row.col.f32.tf32.tf32.f32 "
        "{%0,%1,%2,%3}, {%4,%5,%6,%7}, {%8,%9}, {%0,%1,%2,%3};\n"
        : "+f"(d[0]), "+f"(d[1]), "+f"(d[2]), "+f"(d[3])
        : "r"(a[0]), "r"(a[1]), "r"(a[2]), "r"(a[3]),
          "r"(b[0]), "r"(b[1]));
}

__device__ __forceinline__ void mma_f16(float d[4],
                                        const uint32_t a[4],
                                        const uint32_t b[2]) {
    asm volatile(
        "mma.sync.aligned.m16n8k16.row.col.f32.f16.f16.f32 "
        "{%0,%1,%2,%3}, {%4,%5,%6,%7}, {%8,%9}, {%0,%1,%2,%3};\n"
        : "+f"(d[0]), "+f"(d[1]), "+f"(d[2]), "+f"(d[3])
        : "r"(a[0]), "r"(a[1]), "r"(a[2]), "r"(a[3]),
          "r"(b[0]), "r"(b[1]));
}

__device__ __forceinline__ uint32_t h2_to_u32(__half2 h) {
    return *reinterpret_cast<uint32_t*>(&h);
}

// ---------------------------------------------------------------------------
// FP16 GEMM: C = (A[M,K] @ W[N,K]^T + bias) * scale   (round-14, proven)
// ---------------------------------------------------------------------------
#define HPAD 36

template <int MODE>
__global__ void __launch_bounds__(256, 2)
gemm_f16_kernel(const float* __restrict__ A,
                const float* __restrict__ W,
                const float* __restrict__ bias,
                float* __restrict__ C,
                int M, int N, int K, float scale)
{
    __shared__ __half As[128][HPAD];
    __shared__ __half Bs[128][HPAD];

    const int tid  = threadIdx.x;
    const int warp = tid >> 5;
    const int lane = tid & 31;
    const int wm   = (warp >> 2) * 64;
    const int wn   = (warp & 3) * 32;
    const int g    = lane >> 2;
    const int th   = lane & 3;
    const int m0   = blockIdx.y * 128;
    const int n0   = blockIdx.x * 128;

    float acc[4][4][4];
    #pragma unroll
    for (int mi = 0; mi < 4; mi++)
        #pragma unroll
        for (int ni = 0; ni < 4; ni++)
            #pragma unroll
            for (int r = 0; r < 4; r++) acc[mi][ni][r] = 0.0f;

    const int grow = tid >> 3;
    const int gq   = tid & 7;
    const float* Abase = A + (size_t)(m0 + grow) * K + gq * 4;
    const float* Wbase = W + (size_t)(n0 + grow) * K + gq * 4;

    float4 ra[4], rb[4];
    #pragma unroll
    for (int i = 0; i < 4; i++) {
        ra[i] = *(const float4*)(Abase + (size_t)(i * 32) * K);
        rb[i] = *(const float4*)(Wbase + (size_t)(i * 32) * K);
    }

    for (int k0 = 0; k0 < K; k0 += 32) {
        #pragma unroll
        for (int i = 0; i < 4; i++) {
            const int row = grow + i * 32;
            uint2 ua = make_uint2(
                h2_to_u32(__floats2half2_rn(ra[i].x, ra[i].y)),
                h2_to_u32(__floats2half2_rn(ra[i].z, ra[i].w)));
            uint2 ub = make_uint2(
                h2_to_u32(__floats2half2_rn(rb[i].x, rb[i].y)),
                h2_to_u32(__floats2half2_rn(rb[i].z, rb[i].w)));
            *(uint2*)&As[row][gq * 4] = ua;
            *(uint2*)&Bs[row][gq * 4] = ub;
        }
        __syncthreads();

        if (k0 + 32 < K) {
            #pragma unroll
            for (int i = 0; i < 4; i++) {
                ra[i] = *(const float4*)(Abase + (size_t)(i * 32) * K + k0 + 32);
                rb[i] = *(const float4*)(Wbase + (size_t)(i * 32) * K + k0 + 32);
            }
        }

        #pragma unroll
        for (int ks = 0; ks < 2; ks++) {
            const int kb = ks * 16;
            uint32_t af[4][4], bf[4][2];
            #pragma unroll
            for (int mi = 0; mi < 4; mi++) {
                const int row = wm + mi * 16 + g;
                af[mi][0] = *(const uint32_t*)&As[row    ][kb + 2 * th];
                af[mi][1] = *(const uint32_t*)&As[row + 8][kb + 2 * th];
                af[mi][2] = *(const uint32_t*)&As[row    ][kb + 8 + 2 * th];
                af[mi][3] = *(const uint32_t*)&As[row + 8][kb + 8 + 2 * th];
            }
            #pragma unroll
            for (int ni = 0; ni < 4; ni++) {
                const int row = wn + ni * 8 + g;
                bf[ni][0] = *(const uint32_t*)&Bs[row][kb + 2 * th];
                bf[ni][1] = *(const uint32_t*)&Bs[row][kb + 8 + 2 * th];
            }
            #pragma unroll
            for (int mi = 0; mi < 4; mi++)
                #pragma unroll
                for (int ni = 0; ni < 4; ni++)
                    mma_f16(acc[mi][ni], af[mi], bf[ni]);
        }
        __syncthreads();
    }

    #pragma unroll
    for (int mi = 0; mi < 4; mi++) {
        #pragma unroll
        for (int ni = 0; ni < 4; ni++) {
            const int n  = n0 + wn + ni * 8 + th * 2;
            const float2 bv = *(const float2*)(bias + n);
            const int mA = m0 + wm + mi * 16 + g;
            const int mB = mA + 8;
            float2 vA, vB;
            vA.x = (acc[mi][ni][0] + bv.x) * scale;
            vA.y = (acc[mi][ni][1] + bv.y) * scale;
            vB.x = (acc[mi][ni][2] + bv.x) * scale;
            vB.y = (acc[mi][ni][3] + bv.y) * scale;
            if (MODE == 0) {
                *(float2*)(C + (size_t)mA * N + n) = vA;
                *(float2*)(C + (size_t)mB * N + n) = vB;
            } else {
                const int h = n >> 6;
                const int d = n & (DEPTH - 1);
                {
                    const int b = mA >> 11, s = mA & (SEQ - 1);
                    *(float2*)(C + (((size_t)(b * NHEAD + h)) * SEQ + s) * DEPTH + d) = vA;
                }
                {
                    const int b = mB >> 11, s = mB & (SEQ - 1);
                    *(float2*)(C + (((size_t)(b * NHEAD + h)) * SEQ + s) * DEPTH + d) = vB;
                }
            }
        }
    }
}

// ---------------------------------------------------------------------------
// Tensor-core flash attention (causal), fp16 QK^T + tf32 PV.
//   Br=64 queries per CTA (4 warps x 16 rows), Bc=64 keys per tile.
//   S = Q K^T via fp16 m16n8k16 (Q,K each one fp16-rn rounding = tf32 class).
//   O += P V via tf32 m16n8k8 (P, V rounded once).
//   exp2-domain softmax (log2(e) folded into Q projection scale).
// Smem: K fp16 [64][72], V tf32 [64][72], P tf32 [64][68].
//   K frag LDS word = 36*row + th -> bank = 4g+th+const, all 32 distinct.
// ---------------------------------------------------------------------------
#define KPITCH_H 72   // halves: 64 data + 8 pad (FIX: was 40 < 64 -> row overlap)
#define VPITCH   72   // floats
#define PPITCH   68   // floats

#define ATT_SMEM_FLOATS (64 * KPITCH_H / 2 + 64 * VPITCH + 64 * PPITCH)  // 11264

extern __shared__ float att_smem[];

__global__ void __launch_bounds__(128, 2)
attn_mma_kernel(const float* __restrict__ Q,
                const float* __restrict__ K,
                const float* __restrict__ V,
                float* __restrict__ ctx)
{
    __half* skh = (__half*)att_smem;                  // [64][KPITCH_H] fp16
    float*  sv  = att_smem + 64 * KPITCH_H / 2;       // [64][VPITCH] tf32 bits
    float*  sp  = sv + 64 * VPITCH;                   // [64][PPITCH] tf32 bits

    const int tid  = threadIdx.x;
    const int warp = tid >> 5;
    const int lane = tid & 31;
    const int g    = lane >> 2;
    const int th   = lane & 3;

    const int bh   = blockIdx.x;
    const int qidx = blockIdx.y;
    const int q0   = qidx * 64;
    const int wr   = warp * 16;

    const float* Qb = Q + ((size_t)bh * SEQ + q0 + wr) * DEPTH;
    const float* Kb = K + (size_t)bh * SEQ * DEPTH;
    const float* Vb = V + (size_t)bh * SEQ * DEPTH;

    const int lrow = tid >> 4;
    const int lc4  = tid & 15;

    // ---- Q fragments as fp16 (rows g, g+8), 4 k16-steps x 4 regs ----
    uint32_t qf[4][4];
    #pragma unroll
    for (int j = 0; j < 4; j++) {
        const int kb = j * 16;
        float2 a0 = *(const float2*)(Qb + (size_t)g       * DEPTH + kb + 2 * th);
        float2 a1 = *(const float2*)(Qb + (size_t)(g + 8) * DEPTH + kb + 2 * th);
        float2 a2 = *(const float2*)(Qb + (size_t)g       * DEPTH + kb + 8 + 2 * th);
        float2 a3 = *(const float2*)(Qb + (size_t)(g + 8) * DEPTH + kb + 8 + 2 * th);
        qf[j][0] = h2_to_u32(__floats2half2_rn(a0.x, a0.y));
        qf[j][1] = h2_to_u32(__floats2half2_rn(a1.x, a1.y));
        qf[j][2] = h2_to_u32(__floats2half2_rn(a2.x, a2.y));
        qf[j][3] = h2_to_u32(__floats2half2_rn(a3.x, a3.y));
    }

    float acc[8][4];
    #pragma unroll
    for (int n = 0; n < 8; n++)
        #pragma unroll
        for (int r = 0; r < 4; r++) acc[n][r] = 0.0f;

    float mA = -1e30f, mB = -1e30f, lA = 0.0f, lB = 0.0f;

    const int nkt = qidx + 1;

    for (int kt = 0; kt < nkt; kt++) {
        const int k0 = kt * 64;
        __syncthreads();
        // ---- cooperative K/V tile load: K -> fp16, V -> tf32 ----
        #pragma unroll
        for (int i = 0; i < 8; i++) {
            const int row = lrow + i * 8;
            float4 kxv = *(const float4*)(Kb + (size_t)(k0 + row) * DEPTH + lc4 * 4);
            float4 vxv = *(const float4*)(Vb + (size_t)(k0 + row) * DEPTH + lc4 * 4);
            uint2 kh = make_uint2(
                h2_to_u32(__floats2half2_rn(kxv.x, kxv.y)),
                h2_to_u32(__floats2half2_rn(kxv.z, kxv.w)));
            *(uint2*)&skh[row * KPITCH_H + lc4 * 4] = kh;
            uint4 vq = make_uint4(f2tf32(vxv.x), f2tf32(vxv.y),
                                  f2tf32(vxv.z), f2tf32(vxv.w));
            *(uint4*)&sv[row * VPITCH + lc4 * 4] = vq;
        }
        __syncthreads();

        // ---- S = Q K^T  (fp16 m16n8k16, 32 MMAs) ----
        float s[8][4];
        #pragma unroll
        for (int n = 0; n < 8; n++)
            #pragma unroll
            for (int r = 0; r < 4; r++) s[n][r] = 0.0f;

        #pragma unroll
        for (int j = 0; j < 4; j++) {
            const int kb = j * 16;
            #pragma unroll
            for (int n = 0; n < 8; n++) {
                const __half* kp = &skh[(n * 8 + g) * KPITCH_H + kb + 2 * th];
                uint32_t bf[2] = { *(const uint32_t*)kp,
                                   *(const uint32_t*)(kp + 8) };
                mma_f16(s[n], qf[j], bf);
            }
        }

        // ---- causal mask ----
        const int rA = q0 + wr + g;
        const int rB = rA + 8;
        if (k0 + 63 > q0 + wr) {
            #pragma unroll
            for (int n = 0; n < 8; n++) {
                const int c = k0 + n * 8 + 2 * th;
                if (c     > rA) s[n][0] = -1e30f;
                if (c + 1 > rA) s[n][1] = -1e30f;
                if (c     > rB) s[n][2] = -1e30f;
                if (c + 1 > rB) s[n][3] = -1e30f;
            }
        }

        // ---- online softmax in log2 domain ----
        float rmA = -1e30f, rmB = -1e30f;
        #pragma unroll
        for (int n = 0; n < 8; n++) {
            rmA = fmaxf(rmA, fmaxf(s[n][0], s[n][1]));
            rmB = fmaxf(rmB, fmaxf(s[n][2], s[n][3]));
        }
        rmA = fmaxf(rmA, __shfl_xor_sync(0xffffffffu, rmA, 1));
        rmA = fmaxf(rmA, __shfl_xor_sync(0xffffffffu, rmA, 2));
        rmB = fmaxf(rmB, __shfl_xor_sync(0xffffffffu, rmB, 1));
        rmB = fmaxf(rmB, __shfl_xor_sync(0xffffffffu, rmB, 2));

        const float mnA = fmaxf(mA, rmA);
        const float mnB = fmaxf(mB, rmB);
        const float aA  = exp2f(mA - mnA);
        const float aB  = exp2f(mB - mnB);
        mA = mnA; mB = mnB;

        float sumA = 0.0f, sumB = 0.0f;
        #pragma unroll
        for (int n = 0; n < 8; n++) {
            s[n][0] = exp2f(s[n][0] - mnA); sumA += s[n][0];
            s[n][1] = exp2f(s[n][1] - mnA); sumA += s[n][1];
            s[n][2] = exp2f(s[n][2] - mnB); sumB += s[n][2];
            s[n][3] = exp2f(s[n][3] - mnB); sumB += s[n][3];
        }
        sumA += __shfl_xor_sync(0xffffffffu, sumA, 1);
        sumA += __shfl_xor_sync(0xffffffffu, sumA, 2);
        sumB += __shfl_xor_sync(0xffffffffu, sumB, 1);
        sumB += __shfl_xor_sync(0xffffffffu, sumB, 2);
        lA = lA * aA + sumA;
        lB = lB * aB + sumB;

        #pragma unroll
        for (int n = 0; n < 8; n++) {
            acc[n][0] *= aA; acc[n][1] *= aA;
            acc[n][2] *= aB; acc[n][3] *= aB;
        }

        // ---- P -> smem (tf32 bits); rows are warp-private ----
        #pragma unroll
        for (int n = 0; n < 8; n++) {
            uint2 pA = make_uint2(f2tf32(s[n][0]), f2tf32(s[n][1]));
            uint2 pB = make_uint2(f2tf32(s[n][2]), f2tf32(s[n][3]));
            *(uint2*)&sp[(wr + g    ) * PPITCH + n * 8 + 2 * th] = pA;
            *(uint2*)&sp[(wr + g + 8) * PPITCH + n * 8 + 2 * th] = pB;
        }
        __syncwarp();

        // ---- O += P V  (tf32) ----
        #pragma unroll
        for (int k = 0; k < 8; k++) {
            uint32_t pa[4];
            const float* p0 = &sp[(wr + g    ) * PPITCH + k * 8 + th];
            const float* p8 = &sp[(wr + g + 8) * PPITCH + k * 8 + th];
            pa[0] = __float_as_uint(p0[0]);
            pa[1] = __float_as_uint(p8[0]);
            pa[2] = __float_as_uint(p0[4]);
            pa[3] = __float_as_uint(p8[4]);
            #pragma unroll
            for (int n = 0; n < 8; n++) {
                const float* vp = &sv[(k * 8 + th) * VPITCH + n * 8 + g];
                uint32_t vb[2] = { __float_as_uint(vp[0]),
                                   __float_as_uint(vp[4 * VPITCH]) };
                mma_tf32(acc[n], pa, vb);
            }
        }
    }

    // ---- finalize -> ctx token-major [B,S,1024] ----
    const float iA = 1.0f / lA;
    const float iB = 1.0f / lB;
    const int b = bh >> 4;
    const int h = bh & 15;
    const size_t rowA = (size_t)b * SEQ + q0 + wr + g;
    const size_t rowB = rowA + 8;
    #pragma unroll
    for (int n = 0; n < 8; n++) {
        const int d = h * DEPTH + n * 8 + 2 * th;
        float2 oA = make_float2(acc[n][0] * iA, acc[n][1] * iA);
        float2 oB = make_float2(acc[n][2] * iB, acc[n][3] * iB);
        *(float2*)(ctx + rowA * DMODEL + d) = oA;
        *(float2*)(ctx + rowB * DMODEL + d) = oB;
    }
}

// ---------------------------------------------------------------------------
// Launch
// ---------------------------------------------------------------------------
extern "C" void kernel_launch(void* const* d_in, const int* in_sizes, int n_in,
                              void* d_out, int out_size)
{
    const float* q       = (const float*)d_in[0];
    const float* k       = (const float*)d_in[1];
    const float* v       = (const float*)d_in[2];
    const float* wq_w    = (const float*)d_in[3];
    const float* wq_b    = (const float*)d_in[4];
    const float* wk_w    = (const float*)d_in[5];
    const float* wk_b    = (const float*)d_in[6];
    const float* wv_w    = (const float*)d_in[7];
    const float* wv_b    = (const float*)d_in[8];
    const float* dense_w = (const float*)d_in[9];
    const float* dense_b = (const float*)d_in[10];
    float* out           = (float*)d_out;

    float *qh, *kh, *vh, *ctx;
    cudaGetSymbolAddress((void**)&qh,  g_qh);
    cudaGetSymbolAddress((void**)&kh,  g_kh);
    cudaGetSymbolAddress((void**)&vh,  g_vh);
    cudaGetSymbolAddress((void**)&ctx, g_ctx);

    const dim3 ggrid(DMODEL / 128, NTOK / 128);   // (8, 64)
    const dim3 gblk(256);

    // Projections -> head-major; fold softmax scale * log2(e) into Q.
    gemm_f16_kernel<1><<<ggrid, gblk>>>(q, wq_w, wq_b, qh, NTOK, DMODEL, DMODEL, QK_SCALE_LOG2E);
    gemm_f16_kernel<1><<<ggrid, gblk>>>(k, wk_w, wk_b, kh, NTOK, DMODEL, DMODEL, 1.0f);
    gemm_f16_kernel<1><<<ggrid, gblk>>>(v, wv_w, wv_b, vh, NTOK, DMODEL, DMODEL, 1.0f);

    // Tensor-core flash attention (fp16 QK, Br=64, 2 CTAs/SM)
    const int att_smem_bytes = ATT_SMEM_FLOATS * (int)sizeof(float);  // 45056
    cudaFuncSetAttribute(attn_mma_kernel, cudaFuncAttributeMaxDynamicSharedMemorySize,
                         att_smem_bytes);
    dim3 agrid(BATCH * NHEAD, SEQ / 64);          // (64, 32), bh fastest
    attn_mma_kernel<<<agrid, 128, att_smem_bytes>>>(qh, kh, vh, ctx);

    // Output dense
    gemm_f16_kernel<0><<<ggrid, gblk>>>(ctx, dense_w, dense_b, out, NTOK, DMODEL, DMODEL, 1.0f);
}